// round 12
// baseline (speedup 1.0000x reference)
#include <cuda_runtime.h>
#include <cuda_bf16.h>

// Problem constants
#define BB 2
#define LL 384
#define EE 512
#define HH 8
#define HD 64
#define BH 16            // BB*HH
#define MROWS 768        // BB*LL
#define CATOMS 16        // HD/4
#define JS 8             // j-splits for parallelism
#define JCHUNK 48        // LL/JS
#define EPSQ 1e-6f

// Scratch (no allocations allowed -> device globals)
__device__ float g_q[BH * LL * HD];
__device__ float g_k[BH * LL * HD];
__device__ float g_v[BH * LL * HD];
__device__ float g_part[JS * BH * LL * HD];
__device__ float g_ctx[MROWS * EE];

// ---------------------------------------------------------------------------
// QKV projection: C[m,f] = sum_e x[m,e] * W[f,e], scattered into
// (bh, l, d) head-major layout. grid = (8, 12, 3), block = 256.
// 64x64 output tile, 16-wide K tiles, 4x4 micro-tile per thread.
// ---------------------------------------------------------------------------
__global__ __launch_bounds__(256) void qkv_gemm_kernel(
    const float* __restrict__ x,
    const float* __restrict__ Wq,
    const float* __restrict__ Wk,
    const float* __restrict__ Wv)
{
    __shared__ __align__(16) float As[16][64];
    __shared__ __align__(16) float Bs[16][64];

    const int which = blockIdx.z;
    const float* W = (which == 0) ? Wq : (which == 1 ? Wk : Wv);
    float* out = (which == 0) ? g_q : (which == 1 ? g_k : g_v);

    const int m0 = blockIdx.y * 64;
    const int n0 = blockIdx.x * 64;
    const int tid = threadIdx.x;
    const int tx = tid & 15;
    const int ty = tid >> 4;
    const int lrow = tid >> 2;          // 0..63
    const int lk4 = (tid & 3) << 2;     // 0,4,8,12

    const float* Ap = x + (m0 + lrow) * EE;
    const float* Bp = W + (n0 + lrow) * EE;

    float acc[4][4];
#pragma unroll
    for (int i = 0; i < 4; i++)
#pragma unroll
        for (int j = 0; j < 4; j++) acc[i][j] = 0.0f;

    for (int k0 = 0; k0 < EE; k0 += 16) {
        float4 av = *(const float4*)(Ap + k0 + lk4);
        float4 bv = *(const float4*)(Bp + k0 + lk4);
        As[lk4 + 0][lrow] = av.x; As[lk4 + 1][lrow] = av.y;
        As[lk4 + 2][lrow] = av.z; As[lk4 + 3][lrow] = av.w;
        Bs[lk4 + 0][lrow] = bv.x; Bs[lk4 + 1][lrow] = bv.y;
        Bs[lk4 + 2][lrow] = bv.z; Bs[lk4 + 3][lrow] = bv.w;
        __syncthreads();
#pragma unroll
        for (int kk = 0; kk < 16; kk++) {
            float4 a4 = *(const float4*)&As[kk][ty << 2];
            float4 b4 = *(const float4*)&Bs[kk][tx << 2];
            acc[0][0] += a4.x * b4.x; acc[0][1] += a4.x * b4.y;
            acc[0][2] += a4.x * b4.z; acc[0][3] += a4.x * b4.w;
            acc[1][0] += a4.y * b4.x; acc[1][1] += a4.y * b4.y;
            acc[1][2] += a4.y * b4.z; acc[1][3] += a4.y * b4.w;
            acc[2][0] += a4.z * b4.x; acc[2][1] += a4.z * b4.y;
            acc[2][2] += a4.z * b4.z; acc[2][3] += a4.z * b4.w;
            acc[3][0] += a4.w * b4.x; acc[3][1] += a4.w * b4.y;
            acc[3][2] += a4.w * b4.z; acc[3][3] += a4.w * b4.w;
        }
        __syncthreads();
    }

    // Scatter to head-major (bh, l, d). Tile is fully inside one b (384 % 64
    // == 0) and one head (n0 multiple of 64).
    const int b = m0 / LL;
    const int h = n0 >> 6;
    const int lbase = m0 - b * LL;
#pragma unroll
    for (int i = 0; i < 4; i++) {
        int l = lbase + (ty << 2) + i;
        float4 vst = make_float4(acc[i][0], acc[i][1], acc[i][2], acc[i][3]);
        *(float4*)(out + (((b << 3) + h) * LL + l) * HD + (tx << 2)) = vst;
    }
}

// ---------------------------------------------------------------------------
// Quaternion attention. grid = (6, 16, 8), block = 128.
// 2 threads per query row (8 atoms each), K/V chunk in smem,
// gate mean via one shfl_xor, fp32 FMA throughout.
// ---------------------------------------------------------------------------
__global__ __launch_bounds__(128) void attn_kernel(
    const float* __restrict__ dde_w,
    const float* __restrict__ dde_b)
{
    __shared__ float4 sk[JCHUNK * CATOMS];
    __shared__ float4 sv[JCHUNK * CATOMS];

    const int tid = threadIdx.x;
    const int rb = blockIdx.x;   // row block (64 rows)
    const int bh = blockIdx.y;
    const int js = blockIdx.z;
    const int j0 = js * JCHUNK;

    // Stage K/V chunk: 48 keys x 16 atoms (float4) each
    const float4* kg = (const float4*)(g_k + (bh * LL + j0) * HD);
    const float4* vg = (const float4*)(g_v + (bh * LL + j0) * HD);
    for (int t = tid; t < JCHUNK * CATOMS; t += 128) {
        sk[t] = kg[t];
        sv[t] = vg[t];
    }

    // Gate weights into registers (broadcast loads)
    float w[16], bvec[4];
#pragma unroll
    for (int p = 0; p < 16; p++) w[p] = __ldg(&dde_w[p]);
#pragma unroll
    for (int p = 0; p < 4; p++) bvec[p] = __ldg(&dde_b[p]);

    const int row = rb * 64 + (tid >> 1);
    const int half = tid & 1;

    // q atoms (this thread owns 8 of 16)
    float4 q[8];
    const float4* qg = (const float4*)(g_q + (bh * LL + row) * HD);
#pragma unroll
    for (int a = 0; a < 8; a++) q[a] = qg[half * 8 + a];

    float4 ctx[8];
#pragma unroll
    for (int a = 0; a < 8; a++) ctx[a] = make_float4(0.f, 0.f, 0.f, 0.f);

    __syncthreads();

    for (int jj = 0; jj < JCHUNK; jj++) {
        float4 s[8];
        float g0 = 0.f, g1 = 0.f, g2 = 0.f, g3 = 0.f;
        const float4* kbase = &sk[jj * CATOMS + half * 8];
#pragma unroll
        for (int a = 0; a < 8; a++) {
            float4 kk = kbase[a];
            float4 qa = q[a];
            // Hamilton(q, k); memory order (.x,.y,.z,.w) = (w,x,y,z)
            float hw = qa.x * kk.x - qa.y * kk.y - qa.z * kk.z - qa.w * kk.w;
            float hx = qa.x * kk.y + qa.y * kk.x + qa.z * kk.w - qa.w * kk.z;
            float hy = qa.x * kk.z - qa.y * kk.w + qa.z * kk.x + qa.w * kk.y;
            float hz = qa.x * kk.w + qa.y * kk.z - qa.z * kk.y + qa.w * kk.x;
            float d = hw * hw + hx * hx + hy * hy + hz * hz;
            float inv = __fdividef(1.0f, sqrtf(d) + EPSQ);
            float4 sa = make_float4(hw * inv, hx * inv, hy * inv, hz * inv);
            s[a] = sa;
            g0 += sa.x; g1 += sa.y; g2 += sa.z; g3 += sa.w;
        }
        // Sum across the row's two halves -> full 16-atom sum on both lanes
        g0 += __shfl_xor_sync(0xffffffffu, g0, 1);
        g1 += __shfl_xor_sync(0xffffffffu, g1, 1);
        g2 += __shfl_xor_sync(0xffffffffu, g2, 1);
        g3 += __shfl_xor_sync(0xffffffffu, g3, 1);
        const float inv16 = 1.0f / 16.0f;
        g0 *= inv16; g1 *= inv16; g2 *= inv16; g3 *= inv16;

        float gate[4];
#pragma unroll
        for (int p = 0; p < 4; p++) {
            float z = w[p * 4 + 0] * g0 + w[p * 4 + 1] * g1 +
                      w[p * 4 + 2] * g2 + w[p * 4 + 3] * g3 + bvec[p];
            gate[p] = __fdividef(1.0f, 1.0f + __expf(-z));
        }

        const float4* vbase = &sv[jj * CATOMS + half * 8];
#pragma unroll
        for (int a = 0; a < 8; a++) {
            float4 vv = vbase[a];
            float aw = s[a].x * gate[0];
            float ax = s[a].y * gate[1];
            float ay = s[a].z * gate[2];
            float az = s[a].w * gate[3];
            ctx[a].x += aw * vv.x - ax * vv.y - ay * vv.z - az * vv.w;
            ctx[a].y += aw * vv.y + ax * vv.x + ay * vv.w - az * vv.z;
            ctx[a].z += aw * vv.z - ax * vv.w + ay * vv.x + az * vv.y;
            ctx[a].w += aw * vv.w + ax * vv.z - ay * vv.y + az * vv.x;
        }
    }

    float4* pg = (float4*)(g_part + ((size_t)(js * BH + bh) * LL + row) * HD);
#pragma unroll
    for (int a = 0; a < 8; a++) pg[half * 8 + a] = ctx[a];
}

// ---------------------------------------------------------------------------
// Reduce JS partials + permute (bh,l,d) -> (m, e) GEMM layout.
// grid = 384, block = 256 (one float4 of g_ctx per thread).
// ---------------------------------------------------------------------------
__global__ __launch_bounds__(256) void reduce_kernel()
{
    int idx = blockIdx.x * 256 + threadIdx.x;     // over 98304 float4s
    int flat = idx << 2;
    int m = flat >> 9;            // /512
    int e = flat & 511;
    int b = m / LL;
    int l = m - b * LL;
    int h = e >> 6;
    int d = e & 63;
    float4 acc = make_float4(0.f, 0.f, 0.f, 0.f);
#pragma unroll
    for (int js = 0; js < JS; js++) {
        float4 p = *(const float4*)(g_part +
            ((size_t)(js * BH + (b << 3) + h) * LL + l) * HD + d);
        acc.x += p.x; acc.y += p.y; acc.z += p.z; acc.w += p.w;
    }
    *(float4*)(g_ctx + flat) = acc;
}

// ---------------------------------------------------------------------------
// Output projection: out[m,f] = sum_e ctx[m,e] * Wo[f,e].
// grid = (8, 12), block = 256. Same tiling as qkv_gemm.
// ---------------------------------------------------------------------------
__global__ __launch_bounds__(256) void out_gemm_kernel(
    const float* __restrict__ Wo, float* __restrict__ out)
{
    __shared__ __align__(16) float As[16][64];
    __shared__ __align__(16) float Bs[16][64];

    const int m0 = blockIdx.y * 64;
    const int n0 = blockIdx.x * 64;
    const int tid = threadIdx.x;
    const int tx = tid & 15;
    const int ty = tid >> 4;
    const int lrow = tid >> 2;
    const int lk4 = (tid & 3) << 2;

    const float* Ap = g_ctx + (m0 + lrow) * EE;
    const float* Bp = Wo + (n0 + lrow) * EE;

    float acc[4][4];
#pragma unroll
    for (int i = 0; i < 4; i++)
#pragma unroll
        for (int j = 0; j < 4; j++) acc[i][j] = 0.0f;

    for (int k0 = 0; k0 < EE; k0 += 16) {
        float4 av = *(const float4*)(Ap + k0 + lk4);
        float4 bv = *(const float4*)(Bp + k0 + lk4);
        As[lk4 + 0][lrow] = av.x; As[lk4 + 1][lrow] = av.y;
        As[lk4 + 2][lrow] = av.z; As[lk4 + 3][lrow] = av.w;
        Bs[lk4 + 0][lrow] = bv.x; Bs[lk4 + 1][lrow] = bv.y;
        Bs[lk4 + 2][lrow] = bv.z; Bs[lk4 + 3][lrow] = bv.w;
        __syncthreads();
#pragma unroll
        for (int kk = 0; kk < 16; kk++) {
            float4 a4 = *(const float4*)&As[kk][ty << 2];
            float4 b4 = *(const float4*)&Bs[kk][tx << 2];
            acc[0][0] += a4.x * b4.x; acc[0][1] += a4.x * b4.y;
            acc[0][2] += a4.x * b4.z; acc[0][3] += a4.x * b4.w;
            acc[1][0] += a4.y * b4.x; acc[1][1] += a4.y * b4.y;
            acc[1][2] += a4.y * b4.z; acc[1][3] += a4.y * b4.w;
            acc[2][0] += a4.z * b4.x; acc[2][1] += a4.z * b4.y;
            acc[2][2] += a4.z * b4.z; acc[2][3] += a4.z * b4.w;
            acc[3][0] += a4.w * b4.x; acc[3][1] += a4.w * b4.y;
            acc[3][2] += a4.w * b4.z; acc[3][3] += a4.w * b4.w;
        }
        __syncthreads();
    }

#pragma unroll
    for (int i = 0; i < 4; i++) {
        int m = m0 + (ty << 2) + i;
        float4 vst = make_float4(acc[i][0], acc[i][1], acc[i][2], acc[i][3]);
        *(float4*)(out + m * EE + n0 + (tx << 2)) = vst;
    }
}

// ---------------------------------------------------------------------------
extern "C" void kernel_launch(void* const* d_in, const int* in_sizes, int n_in,
                              void* d_out, int out_size)
{
    const float* x     = (const float*)d_in[0];
    const float* Wq    = (const float*)d_in[1];
    const float* Wk    = (const float*)d_in[2];
    const float* Wv    = (const float*)d_in[3];
    const float* Wo    = (const float*)d_in[4];
    const float* dde_w = (const float*)d_in[5];
    const float* dde_b = (const float*)d_in[6];
    float* out = (float*)d_out;

    qkv_gemm_kernel<<<dim3(8, 12, 3), 256>>>(x, Wq, Wk, Wv);
    attn_kernel<<<dim3(6, BH, JS), 128>>>(dde_w, dde_b);
    reduce_kernel<<<384, 256>>>();
    out_gemm_kernel<<<dim3(8, 12), 256>>>(Wo, out);
}

// round 13
// speedup vs baseline: 1.1279x; 1.1279x over previous
#include <cuda_runtime.h>
#include <cuda_bf16.h>

// Problem constants
#define BB 2
#define LL 384
#define EE 512
#define HH 8
#define HD 64
#define BH 16            // BB*HH
#define MROWS 768        // BB*LL
#define CATOMS 16        // HD/4
#define JS 16            // j-splits for parallelism
#define JCHUNK 24        // LL/JS

// Scratch (no allocations allowed -> device globals)
__device__ float g_q[BH * LL * HD];
__device__ float g_k[BH * LL * HD];
__device__ float g_v[BH * LL * HD];
__device__ float g_part[JS * BH * LL * HD];
__device__ float g_ctx[MROWS * EE];

// ---------------------------------------------------------------------------
// Packed f32x2 helpers (sm_103a FFMA2 path — only reachable via PTX)
// ---------------------------------------------------------------------------
typedef unsigned long long u64;

__device__ __forceinline__ u64 pk2(float lo, float hi) {
    u64 r; asm("mov.b64 %0, {%1, %2};" : "=l"(r) : "f"(lo), "f"(hi)); return r;
}
__device__ __forceinline__ float2 upk2(u64 a) {
    float2 f; asm("mov.b64 {%0, %1}, %2;" : "=f"(f.x), "=f"(f.y) : "l"(a)); return f;
}
__device__ __forceinline__ u64 f2fma(u64 a, u64 b, u64 c) {
    u64 r; asm("fma.rn.f32x2 %0, %1, %2, %3;" : "=l"(r) : "l"(a), "l"(b), "l"(c)); return r;
}
__device__ __forceinline__ u64 f2mul(u64 a, u64 b) {
    u64 r; asm("mul.rn.f32x2 %0, %1, %2;" : "=l"(r) : "l"(a), "l"(b)); return r;
}
__device__ __forceinline__ u64 f2add(u64 a, u64 b) {
    u64 r; asm("add.rn.f32x2 %0, %1, %2;" : "=l"(r) : "l"(a), "l"(b)); return r;
}
__device__ __forceinline__ float frsqrt(float x) {
    float r; asm("rsqrt.approx.f32 %0, %1;" : "=f"(r) : "f"(x)); return r;
}
__device__ __forceinline__ float frcp(float x) {
    float r; asm("rcp.approx.f32 %0, %1;" : "=f"(r) : "f"(x)); return r;
}

// ---------------------------------------------------------------------------
// QKV projection: C[m,f] = sum_e x[m,e] * W[f,e], scattered into (bh,l,d)
// head-major layout. 32x64 tiles -> grid (8, 24, 3), 128 threads.
// Double-buffered smem, f32x2 micro-kernel (4x4 per thread, 2-wide packed).
// ---------------------------------------------------------------------------
__global__ __launch_bounds__(128) void qkv_gemm_kernel(
    const float* __restrict__ x,
    const float* __restrict__ Wq,
    const float* __restrict__ Wk,
    const float* __restrict__ Wv)
{
    __shared__ __align__(16) float As[2][16][32];
    __shared__ __align__(16) float Bs[2][16][64];

    const int which = blockIdx.z;
    const float* W = (which == 0) ? Wq : (which == 1 ? Wk : Wv);
    float* out = (which == 0) ? g_q : (which == 1 ? g_k : g_v);

    const int m0 = blockIdx.y * 32;
    const int n0 = blockIdx.x * 64;
    const int tid = threadIdx.x;
    const int tx = tid & 15;
    const int ty = tid >> 4;

    const int lrow = tid >> 2;          // 0..31
    const int lk4 = (tid & 3) << 2;     // 0,4,8,12

    const float* Ap  = x + (m0 + lrow) * EE + lk4;
    const float* Bp0 = W + (n0 + lrow) * EE + lk4;
    const float* Bp1 = W + (n0 + lrow + 32) * EE + lk4;

    u64 acc[4][2];
#pragma unroll
    for (int i = 0; i < 4; i++) { acc[i][0] = 0ull; acc[i][1] = 0ull; }

    // preload tile 0
    {
        float4 av = *(const float4*)(Ap);
        float4 b0 = *(const float4*)(Bp0);
        float4 b1 = *(const float4*)(Bp1);
        As[0][lk4+0][lrow] = av.x; As[0][lk4+1][lrow] = av.y;
        As[0][lk4+2][lrow] = av.z; As[0][lk4+3][lrow] = av.w;
        Bs[0][lk4+0][lrow] = b0.x; Bs[0][lk4+1][lrow] = b0.y;
        Bs[0][lk4+2][lrow] = b0.z; Bs[0][lk4+3][lrow] = b0.w;
        Bs[0][lk4+0][lrow+32] = b1.x; Bs[0][lk4+1][lrow+32] = b1.y;
        Bs[0][lk4+2][lrow+32] = b1.z; Bs[0][lk4+3][lrow+32] = b1.w;
    }
    __syncthreads();

    int buf = 0;
    for (int t = 0; t < 32; t++) {
        const bool more = (t + 1) < 32;
        float4 na, nb0, nb1;
        if (more) {
            na  = *(const float4*)(Ap  + (t + 1) * 16);
            nb0 = *(const float4*)(Bp0 + (t + 1) * 16);
            nb1 = *(const float4*)(Bp1 + (t + 1) * 16);
        }
#pragma unroll
        for (int kk = 0; kk < 16; kk++) {
            float4 a4 = *(const float4*)&As[buf][kk][ty << 2];
            ulonglong2 b4 = *(const ulonglong2*)&Bs[buf][kk][tx << 2];
            u64 a0 = pk2(a4.x, a4.x), a1 = pk2(a4.y, a4.y);
            u64 a2 = pk2(a4.z, a4.z), a3 = pk2(a4.w, a4.w);
            acc[0][0] = f2fma(a0, b4.x, acc[0][0]); acc[0][1] = f2fma(a0, b4.y, acc[0][1]);
            acc[1][0] = f2fma(a1, b4.x, acc[1][0]); acc[1][1] = f2fma(a1, b4.y, acc[1][1]);
            acc[2][0] = f2fma(a2, b4.x, acc[2][0]); acc[2][1] = f2fma(a2, b4.y, acc[2][1]);
            acc[3][0] = f2fma(a3, b4.x, acc[3][0]); acc[3][1] = f2fma(a3, b4.y, acc[3][1]);
        }
        if (more) {
            int nb = buf ^ 1;
            As[nb][lk4+0][lrow] = na.x;  As[nb][lk4+1][lrow] = na.y;
            As[nb][lk4+2][lrow] = na.z;  As[nb][lk4+3][lrow] = na.w;
            Bs[nb][lk4+0][lrow] = nb0.x; Bs[nb][lk4+1][lrow] = nb0.y;
            Bs[nb][lk4+2][lrow] = nb0.z; Bs[nb][lk4+3][lrow] = nb0.w;
            Bs[nb][lk4+0][lrow+32] = nb1.x; Bs[nb][lk4+1][lrow+32] = nb1.y;
            Bs[nb][lk4+2][lrow+32] = nb1.z; Bs[nb][lk4+3][lrow+32] = nb1.w;
        }
        __syncthreads();
        buf ^= 1;
    }

    // Scatter to head-major (bh, l, d); n0 is a multiple of 64 -> single head.
    const int b = m0 / LL;
    const int h = n0 >> 6;
    const int lbase = m0 - b * LL;
#pragma unroll
    for (int i = 0; i < 4; i++) {
        float2 lo = upk2(acc[i][0]);
        float2 hi = upk2(acc[i][1]);
        int l = lbase + (ty << 2) + i;
        *(float4*)(out + (((b << 3) + h) * LL + l) * HD + (tx << 2)) =
            make_float4(lo.x, lo.y, hi.x, hi.y);
    }
}

// ---------------------------------------------------------------------------
// Quaternion attention, f32x2-packed. grid = (6, 16, JS), block = 128.
// 2 threads per query row; each owns 8 atoms handled as 4 packed atom-pairs.
// K staged in smem component-major with pre-negated x/y/z comps (so all
// Hamilton signs come from operand choice, zero negates in the hot loop).
// ---------------------------------------------------------------------------
__global__ __launch_bounds__(128) void attn_kernel(
    const float* __restrict__ dde_w,
    const float* __restrict__ dde_b)
{
    __shared__ u64 sk[JCHUNK][7][8];   // comps: w,x,y,z,-x,-y,-z  x atom-pairs
    __shared__ u64 sv[JCHUNK][4][8];
    __shared__ float swp[16];          // dde_w / 16 (mean folded in)
    __shared__ float sbp[4];

    const int tid = threadIdx.x;
    const int rb = blockIdx.x;
    const int bh = blockIdx.y;
    const int js = blockIdx.z;
    const int j0 = js * JCHUNK;

    if (tid < 16) swp[tid] = __ldg(&dde_w[tid]) * (1.0f / 16.0f);
    if (tid < 4)  sbp[tid] = __ldg(&dde_b[tid]);

    const float4* kg = (const float4*)(g_k + (bh * LL + j0) * HD);
    const float4* vg = (const float4*)(g_v + (bh * LL + j0) * HD);
    float* skf = (float*)sk;
    float* svf = (float*)sv;
    for (int t = tid; t < JCHUNK * CATOMS; t += 128) {
        int j = t >> 4, a = t & 15, ap = a >> 1, lane = a & 1;
        float4 kq = kg[t];
        float4 vq = vg[t];
        int kb = j * 7 * 16;
        skf[kb + (0*8 + ap)*2 + lane] =  kq.x;
        skf[kb + (1*8 + ap)*2 + lane] =  kq.y;
        skf[kb + (2*8 + ap)*2 + lane] =  kq.z;
        skf[kb + (3*8 + ap)*2 + lane] =  kq.w;
        skf[kb + (4*8 + ap)*2 + lane] = -kq.y;
        skf[kb + (5*8 + ap)*2 + lane] = -kq.z;
        skf[kb + (6*8 + ap)*2 + lane] = -kq.w;
        int vb = j * 4 * 16;
        svf[vb + (0*8 + ap)*2 + lane] = vq.x;
        svf[vb + (1*8 + ap)*2 + lane] = vq.y;
        svf[vb + (2*8 + ap)*2 + lane] = vq.z;
        svf[vb + (3*8 + ap)*2 + lane] = vq.w;
    }

    const int row = rb * 64 + (tid >> 1);
    const int half = tid & 1;

    // q atoms packed: pair p = atoms (half*8 + 2p, +1); lanes = atoms
    const float4* qg = (const float4*)(g_q + (bh * LL + row) * HD);
    u64 qw[4], qx[4], qy[4], qz[4];
#pragma unroll
    for (int p = 0; p < 4; p++) {
        float4 q0 = qg[half * 8 + 2 * p];
        float4 q1 = qg[half * 8 + 2 * p + 1];
        qw[p] = pk2(q0.x, q1.x);
        qx[p] = pk2(q0.y, q1.y);
        qy[p] = pk2(q0.z, q1.z);
        qz[p] = pk2(q0.w, q1.w);
    }

    u64 cw[4], cx[4], cy[4], cz[4];
#pragma unroll
    for (int p = 0; p < 4; p++) { cw[p] = 0ull; cx[p] = 0ull; cy[p] = 0ull; cz[p] = 0ull; }

    __syncthreads();

    for (int jj = 0; jj < JCHUNK; jj++) {
        u64 sW[4], sX[4], sY[4], sZ[4];
        u64 gw = 0ull, gx = 0ull, gy = 0ull, gz = 0ull;
        const u64* kb = &sk[jj][0][half * 4];
#pragma unroll
        for (int p = 0; p < 4; p++) {
            u64 KW = kb[0*8 + p], KX = kb[1*8 + p], KY = kb[2*8 + p], KZ = kb[3*8 + p];
            u64 NKX = kb[4*8 + p], NKY = kb[5*8 + p], NKZ = kb[6*8 + p];
            // Hamilton(q, k), memory order (.x,.y,.z,.w) = (w,x,y,z)
            u64 hw = f2fma(qz[p], NKZ, f2fma(qy[p], NKY, f2fma(qx[p], NKX, f2mul(qw[p], KW))));
            u64 hx = f2fma(qz[p], NKY, f2fma(qy[p], KZ,  f2fma(qx[p], KW,  f2mul(qw[p], KX))));
            u64 hy = f2fma(qz[p], KX,  f2fma(qy[p], KW,  f2fma(qx[p], NKZ, f2mul(qw[p], KY))));
            u64 hz = f2fma(qz[p], KW,  f2fma(qy[p], NKX, f2fma(qx[p], KY,  f2mul(qw[p], KZ))));
            u64 d2 = f2fma(hz, hz, f2fma(hy, hy, f2fma(hx, hx, f2mul(hw, hw))));
            float2 dd = upk2(d2);
            u64 iv = pk2(frsqrt(dd.x), frsqrt(dd.y));
            u64 s0 = f2mul(hw, iv), s1 = f2mul(hx, iv);
            u64 s2 = f2mul(hy, iv), s3 = f2mul(hz, iv);
            sW[p] = s0; sX[p] = s1; sY[p] = s2; sZ[p] = s3;
            gw = f2add(gw, s0); gx = f2add(gx, s1);
            gy = f2add(gy, s2); gz = f2add(gz, s3);
        }
        // Reduce packed lanes + other half-thread -> full 16-atom sums
        float2 t0 = upk2(gw), t1 = upk2(gx), t2 = upk2(gy), t3 = upk2(gz);
        float g0 = t0.x + t0.y, g1 = t1.x + t1.y;
        float g2 = t2.x + t2.y, g3 = t3.x + t3.y;
        g0 += __shfl_xor_sync(0xffffffffu, g0, 1);
        g1 += __shfl_xor_sync(0xffffffffu, g1, 1);
        g2 += __shfl_xor_sync(0xffffffffu, g2, 1);
        g3 += __shfl_xor_sync(0xffffffffu, g3, 1);

        float gate[4];
#pragma unroll
        for (int pp = 0; pp < 4; pp++) {
            float z = swp[pp*4+0] * g0 + swp[pp*4+1] * g1 +
                      swp[pp*4+2] * g2 + swp[pp*4+3] * g3 + sbp[pp];
            gate[pp] = frcp(1.0f + __expf(-z));
        }
        u64 G0 = pk2(gate[0], gate[0]), G1 = pk2(gate[1], gate[1]);
        u64 G2 = pk2(gate[2], gate[2]), G3 = pk2(gate[3], gate[3]);
        u64 N1 = pk2(-gate[1], -gate[1]);
        u64 N2 = pk2(-gate[2], -gate[2]);
        u64 N3 = pk2(-gate[3], -gate[3]);

        const u64* vb = &sv[jj][0][half * 4];
#pragma unroll
        for (int p = 0; p < 4; p++) {
            u64 VW = vb[0*8 + p], VX = vb[1*8 + p], VY = vb[2*8 + p], VZ = vb[3*8 + p];
            u64 aw  = f2mul(sW[p], G0);
            u64 ax  = f2mul(sX[p], G1), nax = f2mul(sX[p], N1);
            u64 ay  = f2mul(sY[p], G2), nay = f2mul(sY[p], N2);
            u64 az  = f2mul(sZ[p], G3), naz = f2mul(sZ[p], N3);
            // ctx += Hamilton(a, v)
            cw[p] = f2fma(naz, VZ, f2fma(nay, VY, f2fma(nax, VX, f2fma(aw, VW, cw[p]))));
            cx[p] = f2fma(naz, VY, f2fma(ay,  VZ, f2fma(ax,  VW, f2fma(aw, VX, cx[p]))));
            cy[p] = f2fma(az,  VX, f2fma(ay,  VW, f2fma(nax, VZ, f2fma(aw, VY, cy[p]))));
            cz[p] = f2fma(az,  VW, f2fma(nay, VX, f2fma(ax,  VY, f2fma(aw, VZ, cz[p]))));
        }
    }

    float4* pg = (float4*)(g_part + ((size_t)(js * BH + bh) * LL + row) * HD);
#pragma unroll
    for (int p = 0; p < 4; p++) {
        float2 w2 = upk2(cw[p]), x2 = upk2(cx[p]);
        float2 y2 = upk2(cy[p]), z2 = upk2(cz[p]);
        pg[half * 8 + 2 * p]     = make_float4(w2.x, x2.x, y2.x, z2.x);
        pg[half * 8 + 2 * p + 1] = make_float4(w2.y, x2.y, y2.y, z2.y);
    }
}

// ---------------------------------------------------------------------------
// Reduce JS partials + permute (bh,l,d) -> (m, e) GEMM layout.
// grid = 384, block = 256 (one float4 of g_ctx per thread).
// ---------------------------------------------------------------------------
__global__ __launch_bounds__(256) void reduce_kernel()
{
    int idx = blockIdx.x * 256 + threadIdx.x;     // over 98304 float4s
    int flat = idx << 2;
    int m = flat >> 9;            // /512
    int e = flat & 511;
    int b = m / LL;
    int l = m - b * LL;
    int h = e >> 6;
    int d = e & 63;
    float4 acc = make_float4(0.f, 0.f, 0.f, 0.f);
#pragma unroll
    for (int js = 0; js < JS; js++) {
        float4 p = *(const float4*)(g_part +
            ((size_t)(js * BH + (b << 3) + h) * LL + l) * HD + d);
        acc.x += p.x; acc.y += p.y; acc.z += p.z; acc.w += p.w;
    }
    *(float4*)(g_ctx + flat) = acc;
}

// ---------------------------------------------------------------------------
// Output projection: out[m,f] = sum_e ctx[m,e] * Wo[f,e].
// 32x64 tiles -> grid (8, 24), 128 threads, double-buffered, f32x2.
// ---------------------------------------------------------------------------
__global__ __launch_bounds__(128) void out_gemm_kernel(
    const float* __restrict__ Wo, float* __restrict__ out)
{
    __shared__ __align__(16) float As[2][16][32];
    __shared__ __align__(16) float Bs[2][16][64];

    const int m0 = blockIdx.y * 32;
    const int n0 = blockIdx.x * 64;
    const int tid = threadIdx.x;
    const int tx = tid & 15;
    const int ty = tid >> 4;
    const int lrow = tid >> 2;
    const int lk4 = (tid & 3) << 2;

    const float* Ap  = g_ctx + (m0 + lrow) * EE + lk4;
    const float* Bp0 = Wo + (n0 + lrow) * EE + lk4;
    const float* Bp1 = Wo + (n0 + lrow + 32) * EE + lk4;

    u64 acc[4][2];
#pragma unroll
    for (int i = 0; i < 4; i++) { acc[i][0] = 0ull; acc[i][1] = 0ull; }

    {
        float4 av = *(const float4*)(Ap);
        float4 b0 = *(const float4*)(Bp0);
        float4 b1 = *(const float4*)(Bp1);
        As[0][lk4+0][lrow] = av.x; As[0][lk4+1][lrow] = av.y;
        As[0][lk4+2][lrow] = av.z; As[0][lk4+3][lrow] = av.w;
        Bs[0][lk4+0][lrow] = b0.x; Bs[0][lk4+1][lrow] = b0.y;
        Bs[0][lk4+2][lrow] = b0.z; Bs[0][lk4+3][lrow] = b0.w;
        Bs[0][lk4+0][lrow+32] = b1.x; Bs[0][lk4+1][lrow+32] = b1.y;
        Bs[0][lk4+2][lrow+32] = b1.z; Bs[0][lk4+3][lrow+32] = b1.w;
    }
    __syncthreads();

    int buf = 0;
    for (int t = 0; t < 32; t++) {
        const bool more = (t + 1) < 32;
        float4 na, nb0, nb1;
        if (more) {
            na  = *(const float4*)(Ap  + (t + 1) * 16);
            nb0 = *(const float4*)(Bp0 + (t + 1) * 16);
            nb1 = *(const float4*)(Bp1 + (t + 1) * 16);
        }
#pragma unroll
        for (int kk = 0; kk < 16; kk++) {
            float4 a4 = *(const float4*)&As[buf][kk][ty << 2];
            ulonglong2 b4 = *(const ulonglong2*)&Bs[buf][kk][tx << 2];
            u64 a0 = pk2(a4.x, a4.x), a1 = pk2(a4.y, a4.y);
            u64 a2 = pk2(a4.z, a4.z), a3 = pk2(a4.w, a4.w);
            acc[0][0] = f2fma(a0, b4.x, acc[0][0]); acc[0][1] = f2fma(a0, b4.y, acc[0][1]);
            acc[1][0] = f2fma(a1, b4.x, acc[1][0]); acc[1][1] = f2fma(a1, b4.y, acc[1][1]);
            acc[2][0] = f2fma(a2, b4.x, acc[2][0]); acc[2][1] = f2fma(a2, b4.y, acc[2][1]);
            acc[3][0] = f2fma(a3, b4.x, acc[3][0]); acc[3][1] = f2fma(a3, b4.y, acc[3][1]);
        }
        if (more) {
            int nb = buf ^ 1;
            As[nb][lk4+0][lrow] = na.x;  As[nb][lk4+1][lrow] = na.y;
            As[nb][lk4+2][lrow] = na.z;  As[nb][lk4+3][lrow] = na.w;
            Bs[nb][lk4+0][lrow] = nb0.x; Bs[nb][lk4+1][lrow] = nb0.y;
            Bs[nb][lk4+2][lrow] = nb0.z; Bs[nb][lk4+3][lrow] = nb0.w;
            Bs[nb][lk4+0][lrow+32] = nb1.x; Bs[nb][lk4+1][lrow+32] = nb1.y;
            Bs[nb][lk4+2][lrow+32] = nb1.z; Bs[nb][lk4+3][lrow+32] = nb1.w;
        }
        __syncthreads();
        buf ^= 1;
    }

#pragma unroll
    for (int i = 0; i < 4; i++) {
        float2 lo = upk2(acc[i][0]);
        float2 hi = upk2(acc[i][1]);
        int m = m0 + (ty << 2) + i;
        *(float4*)(out + m * EE + n0 + (tx << 2)) =
            make_float4(lo.x, lo.y, hi.x, hi.y);
    }
}

// ---------------------------------------------------------------------------
extern "C" void kernel_launch(void* const* d_in, const int* in_sizes, int n_in,
                              void* d_out, int out_size)
{
    const float* x     = (const float*)d_in[0];
    const float* Wq    = (const float*)d_in[1];
    const float* Wk    = (const float*)d_in[2];
    const float* Wv    = (const float*)d_in[3];
    const float* Wo    = (const float*)d_in[4];
    const float* dde_w = (const float*)d_in[5];
    const float* dde_b = (const float*)d_in[6];
    float* out = (float*)d_out;

    qkv_gemm_kernel<<<dim3(8, 24, 3), 128>>>(x, Wq, Wk, Wv);
    attn_kernel<<<dim3(6, BH, JS), 128>>>(dde_w, dde_b);
    reduce_kernel<<<384, 256>>>();
    out_gemm_kernel<<<dim3(8, 24), 128>>>(Wo, out);
}

// round 14
// speedup vs baseline: 1.1925x; 1.0573x over previous
#include <cuda_runtime.h>
#include <cuda_bf16.h>

// Problem constants
#define BB 2
#define LL 384
#define EE 512
#define HH 8
#define HD 64
#define BH 16            // BB*HH
#define MROWS 768        // BB*LL
#define CATOMS 16        // HD/4
#define JS 16            // j-splits for parallelism
#define JCHUNK 24        // LL/JS
#define PSZ (BH * LL * HD)   // one partial slot: 393216 floats

// Scratch (no allocations allowed -> device globals)
__device__ float g_q[BH * LL * HD];
__device__ float g_k[BH * LL * HD];
__device__ float g_v[BH * LL * HD];
__device__ float g_part[JS * BH * LL * HD];   // 25 MB, reused by every stage
__device__ float g_ctx[MROWS * EE];

// ---------------------------------------------------------------------------
// Packed f32x2 helpers (sm_103a FFMA2 path — only reachable via PTX)
// ---------------------------------------------------------------------------
typedef unsigned long long u64;

__device__ __forceinline__ u64 pk2(float lo, float hi) {
    u64 r; asm("mov.b64 %0, {%1, %2};" : "=l"(r) : "f"(lo), "f"(hi)); return r;
}
__device__ __forceinline__ float2 upk2(u64 a) {
    float2 f; asm("mov.b64 {%0, %1}, %2;" : "=f"(f.x), "=f"(f.y) : "l"(a)); return f;
}
__device__ __forceinline__ u64 f2fma(u64 a, u64 b, u64 c) {
    u64 r; asm("fma.rn.f32x2 %0, %1, %2, %3;" : "=l"(r) : "l"(a), "l"(b), "l"(c)); return r;
}
__device__ __forceinline__ u64 f2mul(u64 a, u64 b) {
    u64 r; asm("mul.rn.f32x2 %0, %1, %2;" : "=l"(r) : "l"(a), "l"(b)); return r;
}
__device__ __forceinline__ u64 f2add(u64 a, u64 b) {
    u64 r; asm("add.rn.f32x2 %0, %1, %2;" : "=l"(r) : "l"(a), "l"(b)); return r;
}
__device__ __forceinline__ float frsqrt(float x) {
    float r; asm("rsqrt.approx.f32 %0, %1;" : "=f"(r) : "f"(x)); return r;
}
__device__ __forceinline__ float frcp(float x) {
    float r; asm("rcp.approx.f32 %0, %1;" : "=f"(r) : "f"(x)); return r;
}

// ---------------------------------------------------------------------------
// GEMM tile body: 32x64 output tile, 128 threads, 4x4 micro (f32x2),
// double-buffered smem over NT k-tiles of 16 starting at kbase.
// A: [m, e] row-major, B: [f, e] row-major (inner-product GEMM).
// Result left in acc[4][2] (packed pairs).
// ---------------------------------------------------------------------------
__device__ __forceinline__ void gemm_tile_body(
    const float* __restrict__ Ap, const float* __restrict__ Bp0,
    const float* __restrict__ Bp1, int NT,
    float As[2][16][32], float Bs[2][16][64],
    int lrow, int lk4, int tx, int ty, u64 acc[4][2])
{
#pragma unroll
    for (int i = 0; i < 4; i++) { acc[i][0] = 0ull; acc[i][1] = 0ull; }

    {
        float4 av = *(const float4*)(Ap);
        float4 b0 = *(const float4*)(Bp0);
        float4 b1 = *(const float4*)(Bp1);
        As[0][lk4+0][lrow] = av.x; As[0][lk4+1][lrow] = av.y;
        As[0][lk4+2][lrow] = av.z; As[0][lk4+3][lrow] = av.w;
        Bs[0][lk4+0][lrow] = b0.x; Bs[0][lk4+1][lrow] = b0.y;
        Bs[0][lk4+2][lrow] = b0.z; Bs[0][lk4+3][lrow] = b0.w;
        Bs[0][lk4+0][lrow+32] = b1.x; Bs[0][lk4+1][lrow+32] = b1.y;
        Bs[0][lk4+2][lrow+32] = b1.z; Bs[0][lk4+3][lrow+32] = b1.w;
    }
    __syncthreads();

    int buf = 0;
    for (int t = 0; t < NT; t++) {
        const bool more = (t + 1) < NT;
        float4 na, nb0, nb1;
        if (more) {
            na  = *(const float4*)(Ap  + (t + 1) * 16);
            nb0 = *(const float4*)(Bp0 + (t + 1) * 16);
            nb1 = *(const float4*)(Bp1 + (t + 1) * 16);
        }
#pragma unroll
        for (int kk = 0; kk < 16; kk++) {
            float4 a4 = *(const float4*)&As[buf][kk][ty << 2];
            ulonglong2 b4 = *(const ulonglong2*)&Bs[buf][kk][tx << 2];
            u64 a0 = pk2(a4.x, a4.x), a1 = pk2(a4.y, a4.y);
            u64 a2 = pk2(a4.z, a4.z), a3 = pk2(a4.w, a4.w);
            acc[0][0] = f2fma(a0, b4.x, acc[0][0]); acc[0][1] = f2fma(a0, b4.y, acc[0][1]);
            acc[1][0] = f2fma(a1, b4.x, acc[1][0]); acc[1][1] = f2fma(a1, b4.y, acc[1][1]);
            acc[2][0] = f2fma(a2, b4.x, acc[2][0]); acc[2][1] = f2fma(a2, b4.y, acc[2][1]);
            acc[3][0] = f2fma(a3, b4.x, acc[3][0]); acc[3][1] = f2fma(a3, b4.y, acc[3][1]);
        }
        if (more) {
            int nb = buf ^ 1;
            As[nb][lk4+0][lrow] = na.x;  As[nb][lk4+1][lrow] = na.y;
            As[nb][lk4+2][lrow] = na.z;  As[nb][lk4+3][lrow] = na.w;
            Bs[nb][lk4+0][lrow] = nb0.x; Bs[nb][lk4+1][lrow] = nb0.y;
            Bs[nb][lk4+2][lrow] = nb0.z; Bs[nb][lk4+3][lrow] = nb0.w;
            Bs[nb][lk4+0][lrow+32] = nb1.x; Bs[nb][lk4+1][lrow+32] = nb1.y;
            Bs[nb][lk4+2][lrow+32] = nb1.z; Bs[nb][lk4+3][lrow+32] = nb1.w;
        }
        __syncthreads();
        buf ^= 1;
    }
}

// ---------------------------------------------------------------------------
// QKV projection with split-K=2. grid (8, 24, 6): z = which*2 + ks.
// Partials (head-major scattered layout) -> g_part slots 0..5.
// ---------------------------------------------------------------------------
__global__ __launch_bounds__(128) void qkv_gemm_kernel(
    const float* __restrict__ x,
    const float* __restrict__ Wq,
    const float* __restrict__ Wk,
    const float* __restrict__ Wv)
{
    __shared__ __align__(16) float As[2][16][32];
    __shared__ __align__(16) float Bs[2][16][64];

    const int which = blockIdx.z >> 1;
    const int ks = blockIdx.z & 1;
    const int kbase = ks << 8;                // 0 or 256
    const float* W = (which == 0) ? Wq : (which == 1 ? Wk : Wv);
    float* out = g_part + (size_t)blockIdx.z * PSZ;

    const int m0 = blockIdx.y * 32;
    const int n0 = blockIdx.x * 64;
    const int tid = threadIdx.x;
    const int tx = tid & 15;
    const int ty = tid >> 4;
    const int lrow = tid >> 2;
    const int lk4 = (tid & 3) << 2;

    const float* Ap  = x + (m0 + lrow) * EE + kbase + lk4;
    const float* Bp0 = W + (n0 + lrow) * EE + kbase + lk4;
    const float* Bp1 = W + (n0 + lrow + 32) * EE + kbase + lk4;

    u64 acc[4][2];
    gemm_tile_body(Ap, Bp0, Bp1, 16, As, Bs, lrow, lk4, tx, ty, acc);

    // Scatter to head-major (bh, l, d); n0 multiple of 64 -> single head.
    const int b = m0 / LL;
    const int h = n0 >> 6;
    const int lbase = m0 - b * LL;
#pragma unroll
    for (int i = 0; i < 4; i++) {
        float2 lo = upk2(acc[i][0]);
        float2 hi = upk2(acc[i][1]);
        int l = lbase + (ty << 2) + i;
        *(float4*)(out + (((b << 3) + h) * LL + l) * HD + (tx << 2)) =
            make_float4(lo.x, lo.y, hi.x, hi.y);
    }
}

// Sum the 2 split-K partials into g_q/g_k/g_v. grid (384, 3), 256 threads.
__global__ __launch_bounds__(256) void qkv_sum_kernel()
{
    int i = blockIdx.x * 256 + threadIdx.x;          // over PSZ/4 float4s
    int which = blockIdx.y;
    float4* dst = (float4*)((which == 0) ? g_q : (which == 1 ? g_k : g_v));
    const float4* p0 = (const float4*)(g_part + (size_t)(which * 2) * PSZ);
    const float4* p1 = (const float4*)(g_part + (size_t)(which * 2 + 1) * PSZ);
    float4 a = p0[i], b = p1[i];
    dst[i] = make_float4(a.x + b.x, a.y + b.y, a.z + b.z, a.w + b.w);
}

// ---------------------------------------------------------------------------
// Quaternion attention, f32x2-packed. grid = (6, 16, JS), block = 128.
// ---------------------------------------------------------------------------
__global__ __launch_bounds__(128) void attn_kernel(
    const float* __restrict__ dde_w,
    const float* __restrict__ dde_b)
{
    __shared__ u64 sk[JCHUNK][7][8];   // comps: w,x,y,z,-x,-y,-z  x atom-pairs
    __shared__ u64 sv[JCHUNK][4][8];
    __shared__ float swp[16];          // dde_w / 16 (mean folded in)
    __shared__ float sbp[4];

    const int tid = threadIdx.x;
    const int rb = blockIdx.x;
    const int bh = blockIdx.y;
    const int js = blockIdx.z;
    const int j0 = js * JCHUNK;

    if (tid < 16) swp[tid] = __ldg(&dde_w[tid]) * (1.0f / 16.0f);
    if (tid < 4)  sbp[tid] = __ldg(&dde_b[tid]);

    const float4* kg = (const float4*)(g_k + (bh * LL + j0) * HD);
    const float4* vg = (const float4*)(g_v + (bh * LL + j0) * HD);
    float* skf = (float*)sk;
    float* svf = (float*)sv;
    for (int t = tid; t < JCHUNK * CATOMS; t += 128) {
        int j = t >> 4, a = t & 15, ap = a >> 1, lane = a & 1;
        float4 kq = kg[t];
        float4 vq = vg[t];
        int kb = j * 7 * 16;
        skf[kb + (0*8 + ap)*2 + lane] =  kq.x;
        skf[kb + (1*8 + ap)*2 + lane] =  kq.y;
        skf[kb + (2*8 + ap)*2 + lane] =  kq.z;
        skf[kb + (3*8 + ap)*2 + lane] =  kq.w;
        skf[kb + (4*8 + ap)*2 + lane] = -kq.y;
        skf[kb + (5*8 + ap)*2 + lane] = -kq.z;
        skf[kb + (6*8 + ap)*2 + lane] = -kq.w;
        int vb = j * 4 * 16;
        svf[vb + (0*8 + ap)*2 + lane] = vq.x;
        svf[vb + (1*8 + ap)*2 + lane] = vq.y;
        svf[vb + (2*8 + ap)*2 + lane] = vq.z;
        svf[vb + (3*8 + ap)*2 + lane] = vq.w;
    }

    const int row = rb * 64 + (tid >> 1);
    const int half = tid & 1;

    const float4* qg = (const float4*)(g_q + (bh * LL + row) * HD);
    u64 qw[4], qx[4], qy[4], qz[4];
#pragma unroll
    for (int p = 0; p < 4; p++) {
        float4 q0 = qg[half * 8 + 2 * p];
        float4 q1 = qg[half * 8 + 2 * p + 1];
        qw[p] = pk2(q0.x, q1.x);
        qx[p] = pk2(q0.y, q1.y);
        qy[p] = pk2(q0.z, q1.z);
        qz[p] = pk2(q0.w, q1.w);
    }

    u64 cw[4], cx[4], cy[4], cz[4];
#pragma unroll
    for (int p = 0; p < 4; p++) { cw[p] = 0ull; cx[p] = 0ull; cy[p] = 0ull; cz[p] = 0ull; }

    __syncthreads();

    for (int jj = 0; jj < JCHUNK; jj++) {
        u64 sW[4], sX[4], sY[4], sZ[4];
        u64 gw = 0ull, gx = 0ull, gy = 0ull, gz = 0ull;
        const u64* kb = &sk[jj][0][half * 4];
#pragma unroll
        for (int p = 0; p < 4; p++) {
            u64 KW = kb[0*8 + p], KX = kb[1*8 + p], KY = kb[2*8 + p], KZ = kb[3*8 + p];
            u64 NKX = kb[4*8 + p], NKY = kb[5*8 + p], NKZ = kb[6*8 + p];
            // Hamilton(q, k), memory order (.x,.y,.z,.w) = (w,x,y,z)
            u64 hw = f2fma(qz[p], NKZ, f2fma(qy[p], NKY, f2fma(qx[p], NKX, f2mul(qw[p], KW))));
            u64 hx = f2fma(qz[p], NKY, f2fma(qy[p], KZ,  f2fma(qx[p], KW,  f2mul(qw[p], KX))));
            u64 hy = f2fma(qz[p], KX,  f2fma(qy[p], KW,  f2fma(qx[p], NKZ, f2mul(qw[p], KY))));
            u64 hz = f2fma(qz[p], KW,  f2fma(qy[p], NKX, f2fma(qx[p], KY,  f2mul(qw[p], KZ))));
            u64 d2 = f2fma(hz, hz, f2fma(hy, hy, f2fma(hx, hx, f2mul(hw, hw))));
            float2 dd = upk2(d2);
            u64 iv = pk2(frsqrt(dd.x), frsqrt(dd.y));
            u64 s0 = f2mul(hw, iv), s1 = f2mul(hx, iv);
            u64 s2 = f2mul(hy, iv), s3 = f2mul(hz, iv);
            sW[p] = s0; sX[p] = s1; sY[p] = s2; sZ[p] = s3;
            gw = f2add(gw, s0); gx = f2add(gx, s1);
            gy = f2add(gy, s2); gz = f2add(gz, s3);
        }
        float2 t0 = upk2(gw), t1 = upk2(gx), t2 = upk2(gy), t3 = upk2(gz);
        float g0 = t0.x + t0.y, g1 = t1.x + t1.y;
        float g2 = t2.x + t2.y, g3 = t3.x + t3.y;
        g0 += __shfl_xor_sync(0xffffffffu, g0, 1);
        g1 += __shfl_xor_sync(0xffffffffu, g1, 1);
        g2 += __shfl_xor_sync(0xffffffffu, g2, 1);
        g3 += __shfl_xor_sync(0xffffffffu, g3, 1);

        float gate[4];
#pragma unroll
        for (int pp = 0; pp < 4; pp++) {
            float z = swp[pp*4+0] * g0 + swp[pp*4+1] * g1 +
                      swp[pp*4+2] * g2 + swp[pp*4+3] * g3 + sbp[pp];
            gate[pp] = frcp(1.0f + __expf(-z));
        }
        u64 G0 = pk2(gate[0], gate[0]), G1 = pk2(gate[1], gate[1]);
        u64 G2 = pk2(gate[2], gate[2]), G3 = pk2(gate[3], gate[3]);
        u64 N1 = pk2(-gate[1], -gate[1]);
        u64 N2 = pk2(-gate[2], -gate[2]);
        u64 N3 = pk2(-gate[3], -gate[3]);

        const u64* vb = &sv[jj][0][half * 4];
#pragma unroll
        for (int p = 0; p < 4; p++) {
            u64 VW = vb[0*8 + p], VX = vb[1*8 + p], VY = vb[2*8 + p], VZ = vb[3*8 + p];
            u64 aw  = f2mul(sW[p], G0);
            u64 ax  = f2mul(sX[p], G1), nax = f2mul(sX[p], N1);
            u64 ay  = f2mul(sY[p], G2), nay = f2mul(sY[p], N2);
            u64 az  = f2mul(sZ[p], G3), naz = f2mul(sZ[p], N3);
            cw[p] = f2fma(naz, VZ, f2fma(nay, VY, f2fma(nax, VX, f2fma(aw, VW, cw[p]))));
            cx[p] = f2fma(naz, VY, f2fma(ay,  VZ, f2fma(ax,  VW, f2fma(aw, VX, cx[p]))));
            cy[p] = f2fma(az,  VX, f2fma(ay,  VW, f2fma(nax, VZ, f2fma(aw, VY, cy[p]))));
            cz[p] = f2fma(az,  VW, f2fma(nay, VX, f2fma(ax,  VY, f2fma(aw, VZ, cz[p]))));
        }
    }

    float4* pg = (float4*)(g_part + ((size_t)(js * BH + bh) * LL + row) * HD);
#pragma unroll
    for (int p = 0; p < 4; p++) {
        float2 w2 = upk2(cw[p]), x2 = upk2(cx[p]);
        float2 y2 = upk2(cy[p]), z2 = upk2(cz[p]);
        pg[half * 8 + 2 * p]     = make_float4(w2.x, x2.x, y2.x, z2.x);
        pg[half * 8 + 2 * p + 1] = make_float4(w2.y, x2.y, y2.y, z2.y);
    }
}

// ---------------------------------------------------------------------------
// Reduce JS partials + permute (bh,l,d) -> (m, e) GEMM layout.
// ---------------------------------------------------------------------------
__global__ __launch_bounds__(256) void reduce_kernel()
{
    int idx = blockIdx.x * 256 + threadIdx.x;
    int flat = idx << 2;
    int m = flat >> 9;
    int e = flat & 511;
    int b = m / LL;
    int l = m - b * LL;
    int h = e >> 6;
    int d = e & 63;
    float4 acc = make_float4(0.f, 0.f, 0.f, 0.f);
#pragma unroll
    for (int js = 0; js < JS; js++) {
        float4 p = *(const float4*)(g_part +
            ((size_t)(js * BH + (b << 3) + h) * LL + l) * HD + d);
        acc.x += p.x; acc.y += p.y; acc.z += p.z; acc.w += p.w;
    }
    *(float4*)(g_ctx + flat) = acc;
}

// ---------------------------------------------------------------------------
// Output projection with split-K=4. grid (8, 24, 4): z = ks.
// Partials (plain m-major) -> g_part slots 0..3.
// ---------------------------------------------------------------------------
__global__ __launch_bounds__(128) void out_gemm_kernel(
    const float* __restrict__ Wo)
{
    __shared__ __align__(16) float As[2][16][32];
    __shared__ __align__(16) float Bs[2][16][64];

    const int ks = blockIdx.z;
    const int kbase = ks << 7;                // 0,128,256,384
    float* out = g_part + (size_t)ks * PSZ;

    const int m0 = blockIdx.y * 32;
    const int n0 = blockIdx.x * 64;
    const int tid = threadIdx.x;
    const int tx = tid & 15;
    const int ty = tid >> 4;
    const int lrow = tid >> 2;
    const int lk4 = (tid & 3) << 2;

    const float* Ap  = g_ctx + (m0 + lrow) * EE + kbase + lk4;
    const float* Bp0 = Wo + (n0 + lrow) * EE + kbase + lk4;
    const float* Bp1 = Wo + (n0 + lrow + 32) * EE + kbase + lk4;

    u64 acc[4][2];
    gemm_tile_body(Ap, Bp0, Bp1, 8, As, Bs, lrow, lk4, tx, ty, acc);

#pragma unroll
    for (int i = 0; i < 4; i++) {
        float2 lo = upk2(acc[i][0]);
        float2 hi = upk2(acc[i][1]);
        int m = m0 + (ty << 2) + i;
        *(float4*)(out + m * EE + n0 + (tx << 2)) =
            make_float4(lo.x, lo.y, hi.x, hi.y);
    }
}

// Sum the 4 split-K partials into the final output. grid 384, 256 threads.
__global__ __launch_bounds__(256) void out_sum_kernel(float* __restrict__ out)
{
    int i = blockIdx.x * 256 + threadIdx.x;          // over PSZ/4 float4s
    const float4* p0 = (const float4*)(g_part);
    const float4* p1 = (const float4*)(g_part + (size_t)PSZ);
    const float4* p2 = (const float4*)(g_part + (size_t)2 * PSZ);
    const float4* p3 = (const float4*)(g_part + (size_t)3 * PSZ);
    float4 a = p0[i], b = p1[i], c = p2[i], d = p3[i];
    ((float4*)out)[i] = make_float4(a.x + b.x + c.x + d.x,
                                    a.y + b.y + c.y + d.y,
                                    a.z + b.z + c.z + d.z,
                                    a.w + b.w + c.w + d.w);
}

// ---------------------------------------------------------------------------
extern "C" void kernel_launch(void* const* d_in, const int* in_sizes, int n_in,
                              void* d_out, int out_size)
{
    const float* x     = (const float*)d_in[0];
    const float* Wq    = (const float*)d_in[1];
    const float* Wk    = (const float*)d_in[2];
    const float* Wv    = (const float*)d_in[3];
    const float* Wo    = (const float*)d_in[4];
    const float* dde_w = (const float*)d_in[5];
    const float* dde_b = (const float*)d_in[6];
    float* out = (float*)d_out;

    qkv_gemm_kernel<<<dim3(8, 24, 6), 128>>>(x, Wq, Wk, Wv);
    qkv_sum_kernel<<<dim3(384, 3), 256>>>();
    attn_kernel<<<dim3(6, BH, JS), 128>>>(dde_w, dde_b);
    reduce_kernel<<<384, 256>>>();
    out_gemm_kernel<<<dim3(8, 24, 4), 128>>>(Wo);
    out_sum_kernel<<<384, 256>>>(out);
}

// round 15
// speedup vs baseline: 1.3035x; 1.0931x over previous
#include <cuda_runtime.h>
#include <cuda_bf16.h>

// Problem constants
#define BB 2
#define LL 384
#define EE 512
#define HH 8
#define HD 64
#define BH 16            // BB*HH
#define MROWS 768        // BB*LL
#define CATOMS 16        // HD/4
#define JS 16            // j-splits for parallelism
#define JCHUNK 24        // LL/JS
#define PSZ (BH * LL * HD)   // one partial slot: 393216 floats

// Scratch (no allocations allowed -> device globals)
__device__ float g_q[BH * LL * HD];
__device__ float g_k[BH * LL * HD];
__device__ float g_v[BH * LL * HD];
__device__ float g_part[JS * BH * LL * HD];   // 25 MB, reused by every stage
__device__ float g_ctx[MROWS * EE];

// ---------------------------------------------------------------------------
// Packed f32x2 helpers (sm_103a FFMA2 path — only reachable via PTX)
// ---------------------------------------------------------------------------
typedef unsigned long long u64;

__device__ __forceinline__ u64 pk2(float lo, float hi) {
    u64 r; asm("mov.b64 %0, {%1, %2};" : "=l"(r) : "f"(lo), "f"(hi)); return r;
}
__device__ __forceinline__ float2 upk2(u64 a) {
    float2 f; asm("mov.b64 {%0, %1}, %2;" : "=f"(f.x), "=f"(f.y) : "l"(a)); return f;
}
__device__ __forceinline__ u64 f2fma(u64 a, u64 b, u64 c) {
    u64 r; asm("fma.rn.f32x2 %0, %1, %2, %3;" : "=l"(r) : "l"(a), "l"(b), "l"(c)); return r;
}
__device__ __forceinline__ u64 f2mul(u64 a, u64 b) {
    u64 r; asm("mul.rn.f32x2 %0, %1, %2;" : "=l"(r) : "l"(a), "l"(b)); return r;
}
__device__ __forceinline__ u64 f2add(u64 a, u64 b) {
    u64 r; asm("add.rn.f32x2 %0, %1, %2;" : "=l"(r) : "l"(a), "l"(b)); return r;
}
__device__ __forceinline__ float frsqrt(float x) {
    float r; asm("rsqrt.approx.f32 %0, %1;" : "=f"(r) : "f"(x)); return r;
}
__device__ __forceinline__ float frcp(float x) {
    float r; asm("rcp.approx.f32 %0, %1;" : "=f"(r) : "f"(x)); return r;
}

// ---------------------------------------------------------------------------
// GEMM tile body: 32x64 output tile, 128 threads, 4x4 micro (f32x2),
// double-buffered smem over NT k-tiles of 16.
// ---------------------------------------------------------------------------
__device__ __forceinline__ void gemm_tile_body(
    const float* __restrict__ Ap, const float* __restrict__ Bp0,
    const float* __restrict__ Bp1, int NT,
    float As[2][16][32], float Bs[2][16][64],
    int lrow, int lk4, int tx, int ty, u64 acc[4][2])
{
#pragma unroll
    for (int i = 0; i < 4; i++) { acc[i][0] = 0ull; acc[i][1] = 0ull; }

    {
        float4 av = *(const float4*)(Ap);
        float4 b0 = *(const float4*)(Bp0);
        float4 b1 = *(const float4*)(Bp1);
        As[0][lk4+0][lrow] = av.x; As[0][lk4+1][lrow] = av.y;
        As[0][lk4+2][lrow] = av.z; As[0][lk4+3][lrow] = av.w;
        Bs[0][lk4+0][lrow] = b0.x; Bs[0][lk4+1][lrow] = b0.y;
        Bs[0][lk4+2][lrow] = b0.z; Bs[0][lk4+3][lrow] = b0.w;
        Bs[0][lk4+0][lrow+32] = b1.x; Bs[0][lk4+1][lrow+32] = b1.y;
        Bs[0][lk4+2][lrow+32] = b1.z; Bs[0][lk4+3][lrow+32] = b1.w;
    }
    __syncthreads();

    int buf = 0;
    for (int t = 0; t < NT; t++) {
        const bool more = (t + 1) < NT;
        float4 na, nb0, nb1;
        if (more) {
            na  = *(const float4*)(Ap  + (t + 1) * 16);
            nb0 = *(const float4*)(Bp0 + (t + 1) * 16);
            nb1 = *(const float4*)(Bp1 + (t + 1) * 16);
        }
#pragma unroll
        for (int kk = 0; kk < 16; kk++) {
            float4 a4 = *(const float4*)&As[buf][kk][ty << 2];
            ulonglong2 b4 = *(const ulonglong2*)&Bs[buf][kk][tx << 2];
            u64 a0 = pk2(a4.x, a4.x), a1 = pk2(a4.y, a4.y);
            u64 a2 = pk2(a4.z, a4.z), a3 = pk2(a4.w, a4.w);
            acc[0][0] = f2fma(a0, b4.x, acc[0][0]); acc[0][1] = f2fma(a0, b4.y, acc[0][1]);
            acc[1][0] = f2fma(a1, b4.x, acc[1][0]); acc[1][1] = f2fma(a1, b4.y, acc[1][1]);
            acc[2][0] = f2fma(a2, b4.x, acc[2][0]); acc[2][1] = f2fma(a2, b4.y, acc[2][1]);
            acc[3][0] = f2fma(a3, b4.x, acc[3][0]); acc[3][1] = f2fma(a3, b4.y, acc[3][1]);
        }
        if (more) {
            int nb = buf ^ 1;
            As[nb][lk4+0][lrow] = na.x;  As[nb][lk4+1][lrow] = na.y;
            As[nb][lk4+2][lrow] = na.z;  As[nb][lk4+3][lrow] = na.w;
            Bs[nb][lk4+0][lrow] = nb0.x; Bs[nb][lk4+1][lrow] = nb0.y;
            Bs[nb][lk4+2][lrow] = nb0.z; Bs[nb][lk4+3][lrow] = nb0.w;
            Bs[nb][lk4+0][lrow+32] = nb1.x; Bs[nb][lk4+1][lrow+32] = nb1.y;
            Bs[nb][lk4+2][lrow+32] = nb1.z; Bs[nb][lk4+3][lrow+32] = nb1.w;
        }
        __syncthreads();
        buf ^= 1;
    }
}

// ---------------------------------------------------------------------------
// QKV projection with split-K=2. grid (8, 24, 6): z = which*2 + ks.
// ---------------------------------------------------------------------------
__global__ __launch_bounds__(128) void qkv_gemm_kernel(
    const float* __restrict__ x,
    const float* __restrict__ Wq,
    const float* __restrict__ Wk,
    const float* __restrict__ Wv)
{
    __shared__ __align__(16) float As[2][16][32];
    __shared__ __align__(16) float Bs[2][16][64];

    const int which = blockIdx.z >> 1;
    const int ks = blockIdx.z & 1;
    const int kbase = ks << 8;
    const float* W = (which == 0) ? Wq : (which == 1 ? Wk : Wv);
    float* out = g_part + (size_t)blockIdx.z * PSZ;

    const int m0 = blockIdx.y * 32;
    const int n0 = blockIdx.x * 64;
    const int tid = threadIdx.x;
    const int tx = tid & 15;
    const int ty = tid >> 4;
    const int lrow = tid >> 2;
    const int lk4 = (tid & 3) << 2;

    const float* Ap  = x + (m0 + lrow) * EE + kbase + lk4;
    const float* Bp0 = W + (n0 + lrow) * EE + kbase + lk4;
    const float* Bp1 = W + (n0 + lrow + 32) * EE + kbase + lk4;

    u64 acc[4][2];
    gemm_tile_body(Ap, Bp0, Bp1, 16, As, Bs, lrow, lk4, tx, ty, acc);

    const int b = m0 / LL;
    const int h = n0 >> 6;
    const int lbase = m0 - b * LL;
#pragma unroll
    for (int i = 0; i < 4; i++) {
        float2 lo = upk2(acc[i][0]);
        float2 hi = upk2(acc[i][1]);
        int l = lbase + (ty << 2) + i;
        *(float4*)(out + (((b << 3) + h) * LL + l) * HD + (tx << 2)) =
            make_float4(lo.x, lo.y, hi.x, hi.y);
    }
}

// Sum the 2 split-K partials into g_q/g_k/g_v.
// For Q and K, also normalize each quaternion atom (one float4 == one atom):
// |hamilton(q,k)| = |q||k|, so pre-normalizing q,k makes the interference
// spinor unit-norm by construction — the O(L^2) normalization vanishes.
__global__ __launch_bounds__(256) void qkv_sum_kernel()
{
    int i = blockIdx.x * 256 + threadIdx.x;          // over PSZ/4 float4s
    int which = blockIdx.y;
    float4* dst = (float4*)((which == 0) ? g_q : (which == 1 ? g_k : g_v));
    const float4* p0 = (const float4*)(g_part + (size_t)(which * 2) * PSZ);
    const float4* p1 = (const float4*)(g_part + (size_t)(which * 2 + 1) * PSZ);
    float4 a = p0[i], b = p1[i];
    float4 s = make_float4(a.x + b.x, a.y + b.y, a.z + b.z, a.w + b.w);
    if (which < 2) {
        float n2 = s.x * s.x + s.y * s.y + s.z * s.z + s.w * s.w;
        float r = frsqrt(n2 + 1e-32f);
        s.x *= r; s.y *= r; s.z *= r; s.w *= r;
    }
    dst[i] = s;
}

// ---------------------------------------------------------------------------
// Quaternion attention, f32x2-packed. grid = (6, 16, JS), block = 128.
// q,k arrive pre-normalized -> Hamilton(q,k) is the unit spinor directly.
// K and V both staged 7-component (w,x,y,z,-x,-y,-z) so every sign in both
// Hamilton products comes from operand selection (zero negates in hot loop).
// ---------------------------------------------------------------------------
__global__ __launch_bounds__(128) void attn_kernel(
    const float* __restrict__ dde_w,
    const float* __restrict__ dde_b)
{
    __shared__ u64 sk[JCHUNK][7][8];
    __shared__ u64 sv[JCHUNK][7][8];
    __shared__ float swp[16];          // dde_w / 16 (mean folded in)
    __shared__ float sbp[4];

    const int tid = threadIdx.x;
    const int rb = blockIdx.x;
    const int bh = blockIdx.y;
    const int js = blockIdx.z;
    const int j0 = js * JCHUNK;

    if (tid < 16) swp[tid] = __ldg(&dde_w[tid]) * (1.0f / 16.0f);
    if (tid < 4)  sbp[tid] = __ldg(&dde_b[tid]);

    const float4* kg = (const float4*)(g_k + (bh * LL + j0) * HD);
    const float4* vg = (const float4*)(g_v + (bh * LL + j0) * HD);
    float* skf = (float*)sk;
    float* svf = (float*)sv;
    for (int t = tid; t < JCHUNK * CATOMS; t += 128) {
        int j = t >> 4, a = t & 15, ap = a >> 1, lane = a & 1;
        float4 kq = kg[t];
        float4 vq = vg[t];
        int kb = j * 7 * 16;
        skf[kb + (0*8 + ap)*2 + lane] =  kq.x;
        skf[kb + (1*8 + ap)*2 + lane] =  kq.y;
        skf[kb + (2*8 + ap)*2 + lane] =  kq.z;
        skf[kb + (3*8 + ap)*2 + lane] =  kq.w;
        skf[kb + (4*8 + ap)*2 + lane] = -kq.y;
        skf[kb + (5*8 + ap)*2 + lane] = -kq.z;
        skf[kb + (6*8 + ap)*2 + lane] = -kq.w;
        svf[kb + (0*8 + ap)*2 + lane] =  vq.x;
        svf[kb + (1*8 + ap)*2 + lane] =  vq.y;
        svf[kb + (2*8 + ap)*2 + lane] =  vq.z;
        svf[kb + (3*8 + ap)*2 + lane] =  vq.w;
        svf[kb + (4*8 + ap)*2 + lane] = -vq.y;
        svf[kb + (5*8 + ap)*2 + lane] = -vq.z;
        svf[kb + (6*8 + ap)*2 + lane] = -vq.w;
    }

    const int row = rb * 64 + (tid >> 1);
    const int half = tid & 1;

    const float4* qg = (const float4*)(g_q + (bh * LL + row) * HD);
    u64 qw[4], qx[4], qy[4], qz[4];
#pragma unroll
    for (int p = 0; p < 4; p++) {
        float4 q0 = qg[half * 8 + 2 * p];
        float4 q1 = qg[half * 8 + 2 * p + 1];
        qw[p] = pk2(q0.x, q1.x);
        qx[p] = pk2(q0.y, q1.y);
        qy[p] = pk2(q0.z, q1.z);
        qz[p] = pk2(q0.w, q1.w);
    }

    u64 cw[4], cx[4], cy[4], cz[4];
#pragma unroll
    for (int p = 0; p < 4; p++) { cw[p] = 0ull; cx[p] = 0ull; cy[p] = 0ull; cz[p] = 0ull; }

    __syncthreads();

    for (int jj = 0; jj < JCHUNK; jj++) {
        u64 sW[4], sX[4], sY[4], sZ[4];
        u64 gw = 0ull, gx = 0ull, gy = 0ull, gz = 0ull;
        const u64* kb = &sk[jj][0][half * 4];
#pragma unroll
        for (int p = 0; p < 4; p++) {
            u64 KW = kb[0*8 + p], KX = kb[1*8 + p], KY = kb[2*8 + p], KZ = kb[3*8 + p];
            u64 NKX = kb[4*8 + p], NKY = kb[5*8 + p], NKZ = kb[6*8 + p];
            // Hamilton(q, k) on pre-normalized atoms == unit spinor directly
            u64 hw = f2fma(qz[p], NKZ, f2fma(qy[p], NKY, f2fma(qx[p], NKX, f2mul(qw[p], KW))));
            u64 hx = f2fma(qz[p], NKY, f2fma(qy[p], KZ,  f2fma(qx[p], KW,  f2mul(qw[p], KX))));
            u64 hy = f2fma(qz[p], KX,  f2fma(qy[p], KW,  f2fma(qx[p], NKZ, f2mul(qw[p], KY))));
            u64 hz = f2fma(qz[p], KW,  f2fma(qy[p], NKX, f2fma(qx[p], KY,  f2mul(qw[p], KZ))));
            sW[p] = hw; sX[p] = hx; sY[p] = hy; sZ[p] = hz;
            gw = f2add(gw, hw); gx = f2add(gx, hx);
            gy = f2add(gy, hy); gz = f2add(gz, hz);
        }
        float2 t0 = upk2(gw), t1 = upk2(gx), t2 = upk2(gy), t3 = upk2(gz);
        float g0 = t0.x + t0.y, g1 = t1.x + t1.y;
        float g2 = t2.x + t2.y, g3 = t3.x + t3.y;
        g0 += __shfl_xor_sync(0xffffffffu, g0, 1);
        g1 += __shfl_xor_sync(0xffffffffu, g1, 1);
        g2 += __shfl_xor_sync(0xffffffffu, g2, 1);
        g3 += __shfl_xor_sync(0xffffffffu, g3, 1);

        float gate[4];
#pragma unroll
        for (int pp = 0; pp < 4; pp++) {
            float z = swp[pp*4+0] * g0 + swp[pp*4+1] * g1 +
                      swp[pp*4+2] * g2 + swp[pp*4+3] * g3 + sbp[pp];
            gate[pp] = frcp(1.0f + __expf(-z));
        }
        u64 G0 = pk2(gate[0], gate[0]), G1 = pk2(gate[1], gate[1]);
        u64 G2 = pk2(gate[2], gate[2]), G3 = pk2(gate[3], gate[3]);

        const u64* vb = &sv[jj][0][half * 4];
#pragma unroll
        for (int p = 0; p < 4; p++) {
            u64 VW = vb[0*8 + p], VX = vb[1*8 + p], VY = vb[2*8 + p], VZ = vb[3*8 + p];
            u64 NVX = vb[4*8 + p], NVY = vb[5*8 + p], NVZ = vb[6*8 + p];
            u64 aw = f2mul(sW[p], G0);
            u64 ax = f2mul(sX[p], G1);
            u64 ay = f2mul(sY[p], G2);
            u64 az = f2mul(sZ[p], G3);
            // ctx += Hamilton(a, v); negatives via pre-negated V comps
            cw[p] = f2fma(az, NVZ, f2fma(ay, NVY, f2fma(ax, NVX, f2fma(aw, VW, cw[p]))));
            cx[p] = f2fma(az, NVY, f2fma(ay, VZ,  f2fma(ax, VW,  f2fma(aw, VX, cx[p]))));
            cy[p] = f2fma(az, VX,  f2fma(ay, VW,  f2fma(ax, NVZ, f2fma(aw, VY, cy[p]))));
            cz[p] = f2fma(az, VW,  f2fma(ay, NVX, f2fma(ax, VY,  f2fma(aw, VZ, cz[p]))));
        }
    }

    float4* pg = (float4*)(g_part + ((size_t)(js * BH + bh) * LL + row) * HD);
#pragma unroll
    for (int p = 0; p < 4; p++) {
        float2 w2 = upk2(cw[p]), x2 = upk2(cx[p]);
        float2 y2 = upk2(cy[p]), z2 = upk2(cz[p]);
        pg[half * 8 + 2 * p]     = make_float4(w2.x, x2.x, y2.x, z2.x);
        pg[half * 8 + 2 * p + 1] = make_float4(w2.y, x2.y, y2.y, z2.y);
    }
}

// ---------------------------------------------------------------------------
// Reduce JS partials + permute (bh,l,d) -> (m, e). float2 granularity with
// doubled grid for 2x load-MLP (reduce was latency-limited at occ 28%).
// grid = 768, block = 256.
// ---------------------------------------------------------------------------
__global__ __launch_bounds__(256) void reduce_kernel()
{
    int idx = blockIdx.x * 256 + threadIdx.x;     // over 196608 float2s
    int flat = idx << 1;
    int m = flat >> 9;
    int e = flat & 511;
    int b = m / LL;
    int l = m - b * LL;
    int h = e >> 6;
    int d = e & 63;
    const float* base = g_part + ((size_t)((b << 3) + h) * LL + l) * HD + d;
    float2 acc = make_float2(0.f, 0.f);
#pragma unroll
    for (int js = 0; js < JS; js++) {
        float2 p = *(const float2*)(base + (size_t)js * PSZ);
        acc.x += p.x; acc.y += p.y;
    }
    *(float2*)(g_ctx + flat) = acc;
}

// ---------------------------------------------------------------------------
// Output projection with split-K=4. grid (8, 24, 4).
// ---------------------------------------------------------------------------
__global__ __launch_bounds__(128) void out_gemm_kernel(
    const float* __restrict__ Wo)
{
    __shared__ __align__(16) float As[2][16][32];
    __shared__ __align__(16) float Bs[2][16][64];

    const int ks = blockIdx.z;
    const int kbase = ks << 7;
    float* out = g_part + (size_t)ks * PSZ;

    const int m0 = blockIdx.y * 32;
    const int n0 = blockIdx.x * 64;
    const int tid = threadIdx.x;
    const int tx = tid & 15;
    const int ty = tid >> 4;
    const int lrow = tid >> 2;
    const int lk4 = (tid & 3) << 2;

    const float* Ap  = g_ctx + (m0 + lrow) * EE + kbase + lk4;
    const float* Bp0 = Wo + (n0 + lrow) * EE + kbase + lk4;
    const float* Bp1 = Wo + (n0 + lrow + 32) * EE + kbase + lk4;

    u64 acc[4][2];
    gemm_tile_body(Ap, Bp0, Bp1, 8, As, Bs, lrow, lk4, tx, ty, acc);

#pragma unroll
    for (int i = 0; i < 4; i++) {
        float2 lo = upk2(acc[i][0]);
        float2 hi = upk2(acc[i][1]);
        int m = m0 + (ty << 2) + i;
        *(float4*)(out + m * EE + n0 + (tx << 2)) =
            make_float4(lo.x, lo.y, hi.x, hi.y);
    }
}

// Sum the 4 split-K partials into the final output. grid 384, 256 threads.
__global__ __launch_bounds__(256) void out_sum_kernel(float* __restrict__ out)
{
    int i = blockIdx.x * 256 + threadIdx.x;          // over PSZ/4 float4s
    const float4* p0 = (const float4*)(g_part);
    const float4* p1 = (const float4*)(g_part + (size_t)PSZ);
    const float4* p2 = (const float4*)(g_part + (size_t)2 * PSZ);
    const float4* p3 = (const float4*)(g_part + (size_t)3 * PSZ);
    float4 a = p0[i], b = p1[i], c = p2[i], d = p3[i];
    ((float4*)out)[i] = make_float4(a.x + b.x + c.x + d.x,
                                    a.y + b.y + c.y + d.y,
                                    a.z + b.z + c.z + d.z,
                                    a.w + b.w + c.w + d.w);
}

// ---------------------------------------------------------------------------
extern "C" void kernel_launch(void* const* d_in, const int* in_sizes, int n_in,
                              void* d_out, int out_size)
{
    const float* x     = (const float*)d_in[0];
    const float* Wq    = (const float*)d_in[1];
    const float* Wk    = (const float*)d_in[2];
    const float* Wv    = (const float*)d_in[3];
    const float* Wo    = (const float*)d_in[4];
    const float* dde_w = (const float*)d_in[5];
    const float* dde_b = (const float*)d_in[6];
    float* out = (float*)d_out;

    qkv_gemm_kernel<<<dim3(8, 24, 6), 128>>>(x, Wq, Wk, Wv);
    qkv_sum_kernel<<<dim3(384, 3), 256>>>();
    attn_kernel<<<dim3(6, BH, JS), 128>>>(dde_w, dde_b);
    reduce_kernel<<<768, 256>>>();
    out_gemm_kernel<<<dim3(8, 24, 4), 128>>>(Wo);
    out_sum_kernel<<<384, 256>>>(out);
}

// round 16
// speedup vs baseline: 1.3054x; 1.0015x over previous
#include <cuda_runtime.h>
#include <cuda_bf16.h>

// Problem constants
#define BB 2
#define LL 384
#define EE 512
#define HH 8
#define HD 64
#define BH 16            // BB*HH
#define MROWS 768        // BB*LL
#define CATOMS 16        // HD/4
#define JS 16            // j-splits for parallelism
#define JCHUNK 24        // LL/JS
#define PSZ (BH * LL * HD)   // one partial slot: 393216 floats

// Scratch (no allocations allowed -> device globals)
__device__ float g_q[BH * LL * HD];
__device__ float g_k[BH * LL * HD];
__device__ float g_v[BH * LL * HD];
__device__ float g_part[JS * BH * LL * HD];   // 25 MB, reused by every stage
__device__ float g_ctx[MROWS * EE];

// ---------------------------------------------------------------------------
// Packed f32x2 helpers (sm_103a FFMA2 path — only reachable via PTX)
// ---------------------------------------------------------------------------
typedef unsigned long long u64;

__device__ __forceinline__ u64 pk2(float lo, float hi) {
    u64 r; asm("mov.b64 %0, {%1, %2};" : "=l"(r) : "f"(lo), "f"(hi)); return r;
}
__device__ __forceinline__ float2 upk2(u64 a) {
    float2 f; asm("mov.b64 {%0, %1}, %2;" : "=f"(f.x), "=f"(f.y) : "l"(a)); return f;
}
__device__ __forceinline__ u64 f2fma(u64 a, u64 b, u64 c) {
    u64 r; asm("fma.rn.f32x2 %0, %1, %2, %3;" : "=l"(r) : "l"(a), "l"(b), "l"(c)); return r;
}
__device__ __forceinline__ u64 f2mul(u64 a, u64 b) {
    u64 r; asm("mul.rn.f32x2 %0, %1, %2;" : "=l"(r) : "l"(a), "l"(b)); return r;
}
__device__ __forceinline__ u64 f2add(u64 a, u64 b) {
    u64 r; asm("add.rn.f32x2 %0, %1, %2;" : "=l"(r) : "l"(a), "l"(b)); return r;
}
__device__ __forceinline__ float frsqrt(float x) {
    float r; asm("rsqrt.approx.f32 %0, %1;" : "=f"(r) : "f"(x)); return r;
}
__device__ __forceinline__ float frcp(float x) {
    float r; asm("rcp.approx.f32 %0, %1;" : "=f"(r) : "f"(x)); return r;
}

// ---------------------------------------------------------------------------
// GEMM tile body: 32x64 output tile, 128 threads, 4x4 micro (f32x2),
// double-buffered smem over NT k-tiles of 16.
// ---------------------------------------------------------------------------
__device__ __forceinline__ void gemm_tile_body(
    const float* __restrict__ Ap, const float* __restrict__ Bp0,
    const float* __restrict__ Bp1, int NT,
    float As[2][16][32], float Bs[2][16][64],
    int lrow, int lk4, int tx, int ty, u64 acc[4][2])
{
#pragma unroll
    for (int i = 0; i < 4; i++) { acc[i][0] = 0ull; acc[i][1] = 0ull; }

    {
        float4 av = *(const float4*)(Ap);
        float4 b0 = *(const float4*)(Bp0);
        float4 b1 = *(const float4*)(Bp1);
        As[0][lk4+0][lrow] = av.x; As[0][lk4+1][lrow] = av.y;
        As[0][lk4+2][lrow] = av.z; As[0][lk4+3][lrow] = av.w;
        Bs[0][lk4+0][lrow] = b0.x; Bs[0][lk4+1][lrow] = b0.y;
        Bs[0][lk4+2][lrow] = b0.z; Bs[0][lk4+3][lrow] = b0.w;
        Bs[0][lk4+0][lrow+32] = b1.x; Bs[0][lk4+1][lrow+32] = b1.y;
        Bs[0][lk4+2][lrow+32] = b1.z; Bs[0][lk4+3][lrow+32] = b1.w;
    }
    __syncthreads();

    int buf = 0;
    for (int t = 0; t < NT; t++) {
        const bool more = (t + 1) < NT;
        float4 na, nb0, nb1;
        if (more) {
            na  = *(const float4*)(Ap  + (t + 1) * 16);
            nb0 = *(const float4*)(Bp0 + (t + 1) * 16);
            nb1 = *(const float4*)(Bp1 + (t + 1) * 16);
        }
#pragma unroll
        for (int kk = 0; kk < 16; kk++) {
            float4 a4 = *(const float4*)&As[buf][kk][ty << 2];
            ulonglong2 b4 = *(const ulonglong2*)&Bs[buf][kk][tx << 2];
            u64 a0 = pk2(a4.x, a4.x), a1 = pk2(a4.y, a4.y);
            u64 a2 = pk2(a4.z, a4.z), a3 = pk2(a4.w, a4.w);
            acc[0][0] = f2fma(a0, b4.x, acc[0][0]); acc[0][1] = f2fma(a0, b4.y, acc[0][1]);
            acc[1][0] = f2fma(a1, b4.x, acc[1][0]); acc[1][1] = f2fma(a1, b4.y, acc[1][1]);
            acc[2][0] = f2fma(a2, b4.x, acc[2][0]); acc[2][1] = f2fma(a2, b4.y, acc[2][1]);
            acc[3][0] = f2fma(a3, b4.x, acc[3][0]); acc[3][1] = f2fma(a3, b4.y, acc[3][1]);
        }
        if (more) {
            int nb = buf ^ 1;
            As[nb][lk4+0][lrow] = na.x;  As[nb][lk4+1][lrow] = na.y;
            As[nb][lk4+2][lrow] = na.z;  As[nb][lk4+3][lrow] = na.w;
            Bs[nb][lk4+0][lrow] = nb0.x; Bs[nb][lk4+1][lrow] = nb0.y;
            Bs[nb][lk4+2][lrow] = nb0.z; Bs[nb][lk4+3][lrow] = nb0.w;
            Bs[nb][lk4+0][lrow+32] = nb1.x; Bs[nb][lk4+1][lrow+32] = nb1.y;
            Bs[nb][lk4+2][lrow+32] = nb1.z; Bs[nb][lk4+3][lrow+32] = nb1.w;
        }
        __syncthreads();
        buf ^= 1;
    }
}

// ---------------------------------------------------------------------------
// QKV projection with split-K=2. grid (8, 24, 6): z = which*2 + ks.
// ---------------------------------------------------------------------------
__global__ __launch_bounds__(128) void qkv_gemm_kernel(
    const float* __restrict__ x,
    const float* __restrict__ Wq,
    const float* __restrict__ Wk,
    const float* __restrict__ Wv)
{
    __shared__ __align__(16) float As[2][16][32];
    __shared__ __align__(16) float Bs[2][16][64];

    const int which = blockIdx.z >> 1;
    const int ks = blockIdx.z & 1;
    const int kbase = ks << 8;
    const float* W = (which == 0) ? Wq : (which == 1 ? Wk : Wv);
    float* out = g_part + (size_t)blockIdx.z * PSZ;

    const int m0 = blockIdx.y * 32;
    const int n0 = blockIdx.x * 64;
    const int tid = threadIdx.x;
    const int tx = tid & 15;
    const int ty = tid >> 4;
    const int lrow = tid >> 2;
    const int lk4 = (tid & 3) << 2;

    const float* Ap  = x + (m0 + lrow) * EE + kbase + lk4;
    const float* Bp0 = W + (n0 + lrow) * EE + kbase + lk4;
    const float* Bp1 = W + (n0 + lrow + 32) * EE + kbase + lk4;

    u64 acc[4][2];
    gemm_tile_body(Ap, Bp0, Bp1, 16, As, Bs, lrow, lk4, tx, ty, acc);

    const int b = m0 / LL;
    const int h = n0 >> 6;
    const int lbase = m0 - b * LL;
#pragma unroll
    for (int i = 0; i < 4; i++) {
        float2 lo = upk2(acc[i][0]);
        float2 hi = upk2(acc[i][1]);
        int l = lbase + (ty << 2) + i;
        *(float4*)(out + (((b << 3) + h) * LL + l) * HD + (tx << 2)) =
            make_float4(lo.x, lo.y, hi.x, hi.y);
    }
}

// Sum the 2 split-K partials into g_q/g_k/g_v.
// For Q and K, also normalize each quaternion atom: |hamilton(q,k)|=|q||k|,
// so pre-normalizing q,k makes the interference spinor unit-norm by
// construction — the O(L^2) normalization vanishes.
__global__ __launch_bounds__(256) void qkv_sum_kernel()
{
    int i = blockIdx.x * 256 + threadIdx.x;          // over PSZ/4 float4s
    int which = blockIdx.y;
    float4* dst = (float4*)((which == 0) ? g_q : (which == 1 ? g_k : g_v));
    const float4* p0 = (const float4*)(g_part + (size_t)(which * 2) * PSZ);
    const float4* p1 = (const float4*)(g_part + (size_t)(which * 2 + 1) * PSZ);
    float4 a = p0[i], b = p1[i];
    float4 s = make_float4(a.x + b.x, a.y + b.y, a.z + b.z, a.w + b.w);
    if (which < 2) {
        float n2 = s.x * s.x + s.y * s.y + s.z * s.z + s.w * s.w;
        float r = frsqrt(n2 + 1e-32f);
        s.x *= r; s.y *= r; s.z *= r; s.w *= r;
    }
    dst[i] = s;
}

// ---------------------------------------------------------------------------
// Quaternion attention, f32x2-packed. grid = (6, 16, JS), block = 128.
// q,k pre-normalized -> Hamilton(q,k) is the unit spinor directly.
// K and V staged 7-component (w,x,y,z,-x,-y,-z): all Hamilton signs come
// from operand selection. jj loop unrolled x2 so ptxas can overlap one
// iteration's independent FMA work with the other's shfl/MUFU gate chain.
// Partials stored directly in (js, m, e) layout so the reduce is linear.
// ---------------------------------------------------------------------------
__global__ __launch_bounds__(128) void attn_kernel(
    const float* __restrict__ dde_w,
    const float* __restrict__ dde_b)
{
    __shared__ u64 sk[JCHUNK][7][8];
    __shared__ u64 sv[JCHUNK][7][8];
    __shared__ float swp[16];          // dde_w / 16 (mean folded in)
    __shared__ float sbp[4];

    const int tid = threadIdx.x;
    const int rb = blockIdx.x;
    const int bh = blockIdx.y;
    const int js = blockIdx.z;
    const int j0 = js * JCHUNK;

    if (tid < 16) swp[tid] = __ldg(&dde_w[tid]) * (1.0f / 16.0f);
    if (tid < 4)  sbp[tid] = __ldg(&dde_b[tid]);

    const float4* kg = (const float4*)(g_k + (bh * LL + j0) * HD);
    const float4* vg = (const float4*)(g_v + (bh * LL + j0) * HD);
    float* skf = (float*)sk;
    float* svf = (float*)sv;
    for (int t = tid; t < JCHUNK * CATOMS; t += 128) {
        int j = t >> 4, a = t & 15, ap = a >> 1, lane = a & 1;
        float4 kq = kg[t];
        float4 vq = vg[t];
        int kb = j * 7 * 16;
        skf[kb + (0*8 + ap)*2 + lane] =  kq.x;
        skf[kb + (1*8 + ap)*2 + lane] =  kq.y;
        skf[kb + (2*8 + ap)*2 + lane] =  kq.z;
        skf[kb + (3*8 + ap)*2 + lane] =  kq.w;
        skf[kb + (4*8 + ap)*2 + lane] = -kq.y;
        skf[kb + (5*8 + ap)*2 + lane] = -kq.z;
        skf[kb + (6*8 + ap)*2 + lane] = -kq.w;
        svf[kb + (0*8 + ap)*2 + lane] =  vq.x;
        svf[kb + (1*8 + ap)*2 + lane] =  vq.y;
        svf[kb + (2*8 + ap)*2 + lane] =  vq.z;
        svf[kb + (3*8 + ap)*2 + lane] =  vq.w;
        svf[kb + (4*8 + ap)*2 + lane] = -vq.y;
        svf[kb + (5*8 + ap)*2 + lane] = -vq.z;
        svf[kb + (6*8 + ap)*2 + lane] = -vq.w;
    }

    const int row = rb * 64 + (tid >> 1);
    const int half = tid & 1;

    const float4* qg = (const float4*)(g_q + (bh * LL + row) * HD);
    u64 qw[4], qx[4], qy[4], qz[4];
#pragma unroll
    for (int p = 0; p < 4; p++) {
        float4 q0 = qg[half * 8 + 2 * p];
        float4 q1 = qg[half * 8 + 2 * p + 1];
        qw[p] = pk2(q0.x, q1.x);
        qx[p] = pk2(q0.y, q1.y);
        qy[p] = pk2(q0.z, q1.z);
        qz[p] = pk2(q0.w, q1.w);
    }

    u64 cw[4], cx[4], cy[4], cz[4];
#pragma unroll
    for (int p = 0; p < 4; p++) { cw[p] = 0ull; cx[p] = 0ull; cy[p] = 0ull; cz[p] = 0ull; }

    __syncthreads();

#pragma unroll 2
    for (int jj = 0; jj < JCHUNK; jj++) {
        u64 sW[4], sX[4], sY[4], sZ[4];
        u64 gw = 0ull, gx = 0ull, gy = 0ull, gz = 0ull;
        const u64* kb = &sk[jj][0][half * 4];
#pragma unroll
        for (int p = 0; p < 4; p++) {
            u64 KW = kb[0*8 + p], KX = kb[1*8 + p], KY = kb[2*8 + p], KZ = kb[3*8 + p];
            u64 NKX = kb[4*8 + p], NKY = kb[5*8 + p], NKZ = kb[6*8 + p];
            // Hamilton(q, k) on pre-normalized atoms == unit spinor directly
            u64 hw = f2fma(qz[p], NKZ, f2fma(qy[p], NKY, f2fma(qx[p], NKX, f2mul(qw[p], KW))));
            u64 hx = f2fma(qz[p], NKY, f2fma(qy[p], KZ,  f2fma(qx[p], KW,  f2mul(qw[p], KX))));
            u64 hy = f2fma(qz[p], KX,  f2fma(qy[p], KW,  f2fma(qx[p], NKZ, f2mul(qw[p], KY))));
            u64 hz = f2fma(qz[p], KW,  f2fma(qy[p], NKX, f2fma(qx[p], KY,  f2mul(qw[p], KZ))));
            sW[p] = hw; sX[p] = hx; sY[p] = hy; sZ[p] = hz;
            gw = f2add(gw, hw); gx = f2add(gx, hx);
            gy = f2add(gy, hy); gz = f2add(gz, hz);
        }
        float2 t0 = upk2(gw), t1 = upk2(gx), t2 = upk2(gy), t3 = upk2(gz);
        float g0 = t0.x + t0.y, g1 = t1.x + t1.y;
        float g2 = t2.x + t2.y, g3 = t3.x + t3.y;
        g0 += __shfl_xor_sync(0xffffffffu, g0, 1);
        g1 += __shfl_xor_sync(0xffffffffu, g1, 1);
        g2 += __shfl_xor_sync(0xffffffffu, g2, 1);
        g3 += __shfl_xor_sync(0xffffffffu, g3, 1);

        float gate[4];
#pragma unroll
        for (int pp = 0; pp < 4; pp++) {
            float z = swp[pp*4+0] * g0 + swp[pp*4+1] * g1 +
                      swp[pp*4+2] * g2 + swp[pp*4+3] * g3 + sbp[pp];
            gate[pp] = frcp(1.0f + __expf(-z));
        }
        u64 G0 = pk2(gate[0], gate[0]), G1 = pk2(gate[1], gate[1]);
        u64 G2 = pk2(gate[2], gate[2]), G3 = pk2(gate[3], gate[3]);

        const u64* vb = &sv[jj][0][half * 4];
#pragma unroll
        for (int p = 0; p < 4; p++) {
            u64 VW = vb[0*8 + p], VX = vb[1*8 + p], VY = vb[2*8 + p], VZ = vb[3*8 + p];
            u64 NVX = vb[4*8 + p], NVY = vb[5*8 + p], NVZ = vb[6*8 + p];
            u64 aw = f2mul(sW[p], G0);
            u64 ax = f2mul(sX[p], G1);
            u64 ay = f2mul(sY[p], G2);
            u64 az = f2mul(sZ[p], G3);
            // ctx += Hamilton(a, v); negatives via pre-negated V comps
            cw[p] = f2fma(az, NVZ, f2fma(ay, NVY, f2fma(ax, NVX, f2fma(aw, VW, cw[p]))));
            cx[p] = f2fma(az, NVY, f2fma(ay, VZ,  f2fma(ax, VW,  f2fma(aw, VX, cx[p]))));
            cy[p] = f2fma(az, VX,  f2fma(ay, VW,  f2fma(ax, NVZ, f2fma(aw, VY, cy[p]))));
            cz[p] = f2fma(az, VW,  f2fma(ay, NVX, f2fma(ax, VY,  f2fma(aw, VZ, cz[p]))));
        }
    }

    // Store partials directly in (js, m, e) layout: m = b*LL+row, e = h*64+d.
    // Same coalescing as before, but makes the reduce perfectly linear.
    const int b = bh >> 3;
    const int h = bh & 7;
    float4* pg = (float4*)(g_part + (size_t)js * PSZ +
                           ((size_t)(b * LL + row)) * EE + h * HD);
#pragma unroll
    for (int p = 0; p < 4; p++) {
        float2 w2 = upk2(cw[p]), x2 = upk2(cx[p]);
        float2 y2 = upk2(cy[p]), z2 = upk2(cz[p]);
        pg[half * 8 + 2 * p]     = make_float4(w2.x, x2.x, y2.x, z2.x);
        pg[half * 8 + 2 * p + 1] = make_float4(w2.y, x2.y, y2.y, z2.y);
    }
}

// ---------------------------------------------------------------------------
// Reduce JS partials (already stored in (m,e) layout -> fully linear
// streams, zero index math). grid = 384, block = 256, float4 each.
// ---------------------------------------------------------------------------
__global__ __launch_bounds__(256) void reduce_kernel()
{
    int i = blockIdx.x * 256 + threadIdx.x;     // over 98304 float4s
    float4 acc = make_float4(0.f, 0.f, 0.f, 0.f);
#pragma unroll
    for (int js = 0; js < JS; js++) {
        float4 p = ((const float4*)(g_part + (size_t)js * PSZ))[i];
        acc.x += p.x; acc.y += p.y; acc.z += p.z; acc.w += p.w;
    }
    ((float4*)g_ctx)[i] = acc;
}

// ---------------------------------------------------------------------------
// Output projection with split-K=4. grid (8, 24, 4).
// ---------------------------------------------------------------------------
__global__ __launch_bounds__(128) void out_gemm_kernel(
    const float* __restrict__ Wo)
{
    __shared__ __align__(16) float As[2][16][32];
    __shared__ __align__(16) float Bs[2][16][64];

    const int ks = blockIdx.z;
    const int kbase = ks << 7;
    float* out = g_part + (size_t)ks * PSZ;

    const int m0 = blockIdx.y * 32;
    const int n0 = blockIdx.x * 64;
    const int tid = threadIdx.x;
    const int tx = tid & 15;
    const int ty = tid >> 4;
    const int lrow = tid >> 2;
    const int lk4 = (tid & 3) << 2;

    const float* Ap  = g_ctx + (m0 + lrow) * EE + kbase + lk4;
    const float* Bp0 = Wo + (n0 + lrow) * EE + kbase + lk4;
    const float* Bp1 = Wo + (n0 + lrow + 32) * EE + kbase + lk4;

    u64 acc[4][2];
    gemm_tile_body(Ap, Bp0, Bp1, 8, As, Bs, lrow, lk4, tx, ty, acc);

#pragma unroll
    for (int i = 0; i < 4; i++) {
        float2 lo = upk2(acc[i][0]);
        float2 hi = upk2(acc[i][1]);
        int m = m0 + (ty << 2) + i;
        *(float4*)(out + m * EE + n0 + (tx << 2)) =
            make_float4(lo.x, lo.y, hi.x, hi.y);
    }
}

// Sum the 4 split-K partials into the final output. grid 384, 256 threads.
__global__ __launch_bounds__(256) void out_sum_kernel(float* __restrict__ out)
{
    int i = blockIdx.x * 256 + threadIdx.x;          // over PSZ/4 float4s
    const float4* p0 = (const float4*)(g_part);
    const float4* p1 = (const float4*)(g_part + (size_t)PSZ);
    const float4* p2 = (const float4*)(g_part + (size_t)2 * PSZ);
    const float4* p3 = (const float4*)(g_part + (size_t)3 * PSZ);
    float4 a = p0[i], b = p1[i], c = p2[i], d = p3[i];
    ((float4*)out)[i] = make_float4(a.x + b.x + c.x + d.x,
                                    a.y + b.y + c.y + d.y,
                                    a.z + b.z + c.z + d.z,
                                    a.w + b.w + c.w + d.w);
}

// ---------------------------------------------------------------------------
extern "C" void kernel_launch(void* const* d_in, const int* in_sizes, int n_in,
                              void* d_out, int out_size)
{
    const float* x     = (const float*)d_in[0];
    const float* Wq    = (const float*)d_in[1];
    const float* Wk    = (const float*)d_in[2];
    const float* Wv    = (const float*)d_in[3];
    const float* Wo    = (const float*)d_in[4];
    const float* dde_w = (const float*)d_in[5];
    const float* dde_b = (const float*)d_in[6];
    float* out = (float*)d_out;

    qkv_gemm_kernel<<<dim3(8, 24, 6), 128>>>(x, Wq, Wk, Wv);
    qkv_sum_kernel<<<dim3(384, 3), 256>>>();
    attn_kernel<<<dim3(6, BH, JS), 128>>>(dde_w, dde_b);
    reduce_kernel<<<384, 256>>>();
    out_gemm_kernel<<<dim3(8, 24, 4), 128>>>(Wo);
    out_sum_kernel<<<384, 256>>>(out);
}